// round 9
// baseline (speedup 1.0000x reference)
#include <cuda_runtime.h>
#include <cuda_fp16.h>
#include <math.h>
#include <stdint.h>

// Problem constants
#define BB 4
#define TT 1024
#define DD 1024
#define HH 16
#define HDIM 64
#define LL 8
#define VV 50257
#define VPAD 50304
#define ROWS (BB*TT)            // 4096
#define SCALE_ATT 0.07216878364870322f  // 1/sqrt(192)

// ---------------------------------------------------------------------------
// Scratch (static device globals; no runtime allocation)
// ---------------------------------------------------------------------------
__device__ float g_x   [ (size_t)ROWS * DD     ];   // residual stream (fp32)
__device__ float g_qkv [ (size_t)ROWS * 3 * DD ];   // qkv (fp32)
__device__ float g_nll [ ROWS ];
// fp16 hi/lo split activations
__device__ __half g_hhi [ (size_t)ROWS * DD ];
__device__ __half g_hlo [ (size_t)ROWS * DD ];
__device__ __half g_yhi [ (size_t)ROWS * DD ];
__device__ __half g_ylo [ (size_t)ROWS * DD ];
__device__ __half g_mhi [ (size_t)ROWS * 4 * DD ];
__device__ __half g_mlo [ (size_t)ROWS * 4 * DD ];
__device__ __half g_xhi [ (size_t)ROWS * DD ];
__device__ __half g_xlo [ (size_t)ROWS * DD ];
// fp16 hi/lo split transposed weights ([N,K] row-major)
__device__ __half g_wqkvThi [ (size_t)LL * 3*DD * DD ];
__device__ __half g_wqkvTlo [ (size_t)LL * 3*DD * DD ];
__device__ __half g_wprojThi[ (size_t)LL * DD * DD ];
__device__ __half g_wprojTlo[ (size_t)LL * DD * DD ];
__device__ __half g_w1Thi   [ (size_t)LL * 4*DD * DD ];
__device__ __half g_w1Tlo   [ (size_t)LL * 4*DD * DD ];
__device__ __half g_w2Thi   [ (size_t)LL * DD * 4*DD ];
__device__ __half g_w2Tlo   [ (size_t)LL * DD * 4*DD ];
__device__ __half g_lmwThi  [ (size_t)VPAD * DD ];
__device__ __half g_lmwTlo  [ (size_t)VPAD * DD ];

// ---------------------------------------------------------------------------
// helpers
// ---------------------------------------------------------------------------
__device__ __forceinline__ uint32_t smem_u32(const void* p) {
    uint32_t a;
    asm("{ .reg .u64 t; cvta.to.shared.u64 t, %1; cvt.u32.u64 %0, t; }"
        : "=r"(a) : "l"(p));
    return a;
}
__device__ __forceinline__ uint32_t pack2_hi(float x, float y, float& rx, float& ry) {
    __half hx = __float2half_rn(x);
    __half hy = __float2half_rn(y);
    rx = x - __half2float(hx);
    ry = y - __half2float(hy);
    return (uint32_t)__half_as_ushort(hx) | ((uint32_t)__half_as_ushort(hy) << 16);
}
__device__ __forceinline__ uint32_t pack2(float x, float y) {
    __half hx = __float2half_rn(x);
    __half hy = __float2half_rn(y);
    return (uint32_t)__half_as_ushort(hx) | ((uint32_t)__half_as_ushort(hy) << 16);
}

// fp16 inputs, fp32 accumulate (main term)
#define MMA_F32(d, a, b) \
    asm volatile("mma.sync.aligned.m16n8k16.row.col.f32.f16.f16.f32 " \
        "{%0,%1,%2,%3}, {%4,%5,%6,%7}, {%8,%9}, {%0,%1,%2,%3};" \
        : "+f"((d)[0]), "+f"((d)[1]), "+f"((d)[2]), "+f"((d)[3]) \
        : "r"((a)[0]), "r"((a)[1]), "r"((a)[2]), "r"((a)[3]), \
          "r"((b)[0]), "r"((b)[1]))

// fp16 inputs, fp16 accumulate (correction terms; 2 regs = 4 halves)
#define MMA_F16(d, a, b) \
    asm volatile("mma.sync.aligned.m16n8k16.row.col.f16.f16.f16.f16 " \
        "{%0,%1}, {%2,%3,%4,%5}, {%6,%7}, {%0,%1};" \
        : "+r"((d)[0]), "+r"((d)[1]) \
        : "r"((a)[0]), "r"((a)[1]), "r"((a)[2]), "r"((a)[3]), \
          "r"((b)[0]), "r"((b)[1]))

#define LDSM4(r0, r1, r2, r3, addr) \
    asm volatile("ldmatrix.sync.aligned.m8n8.x4.shared.b16 {%0,%1,%2,%3}, [%4];" \
        : "=r"(r0), "=r"(r1), "=r"(r2), "=r"(r3) : "r"(addr))

__device__ __forceinline__ void cp16(uint32_t d, const void* g) {
    asm volatile("cp.async.cg.shared.global [%0], [%1], 16;" :: "r"(d), "l"(g));
}
#define CP_COMMIT() asm volatile("cp.async.commit_group;" ::: "memory")
#define CP_WAIT0()  asm volatile("cp.async.wait_group 0;" ::: "memory")
#define CP_WAIT1()  asm volatile("cp.async.wait_group 1;" ::: "memory")

// ---------------------------------------------------------------------------
// fp16-split tensor GEMM: C = A @ Bt^T. Main term fp32-accum, cross terms
// fp16-accum (2x rate if HW supports). CTA tile 128x128, K-chunk 32,
// 2-stage cp.async, 512 threads, warp grid 4x4 (warp tile 32x32).
// EPI: 0=bias->f32, 1=bias+relu->fp16 split, 2=bias+residual->f32.
// ---------------------------------------------------------------------------
#define TILEB 10240
#define BUFB  (4*TILEB)        // 40960
#define SMEM_DYN (2*BUFB)      // 81920; epilogue Cs (128*132*4=67584) fits

template<int EPI>
__global__ __launch_bounds__(512) void hgemm_kernel(
    int M, int N, int K,
    const __half* __restrict__ Ahi, const __half* __restrict__ Alo,
    const __half* __restrict__ Bhi, const __half* __restrict__ Blo,
    const float* __restrict__ bias, const float* __restrict__ res,
    float* __restrict__ C,
    __half* __restrict__ Chi, __half* __restrict__ Clo)
{
    extern __shared__ __align__(128) char smem[];
    const uint32_t sb = smem_u32(smem);
    const int tid  = threadIdx.x;
    const int wid  = tid >> 5;
    const int lane = tid & 31;
    const int mbase = blockIdx.x * 128;
    const int nbase = blockIdx.y * 128;
    const int warp_m = wid & 3;
    const int warp_n = wid >> 2;
    const int g = lane >> 2;
    const int q = lane & 3;

    const uint32_t aoff = (uint32_t)(warp_m*32 + (lane & 15)) * 80
                        + ((lane >> 4) & 1) * 16;
    const uint32_t boff = 2*TILEB
                        + (uint32_t)(warp_n*32 + (lane & 7) + ((lane >> 4) & 1)*8) * 80
                        + ((lane >> 3) & 1) * 16;

    float acc[2][4][4];
    uint32_t acch[2][4][2];
    #pragma unroll
    for (int m = 0; m < 2; m++)
        #pragma unroll
        for (int n = 0; n < 4; n++) {
            #pragma unroll
            for (int r = 0; r < 4; r++) acc[m][n][r] = 0.0f;
            acch[m][n][0] = 0u; acch[m][n][1] = 0u;
        }

    const int nch = K >> 5;

    auto issue = [&](uint32_t dstbase, int k0) {
        const int row = tid >> 2, seg = tid & 3;
        const uint32_t doff = (uint32_t)row*80 + seg*16;
        const int soff = k0 + seg*8;
        cp16(dstbase + doff,           Ahi + (size_t)(mbase+row)*K + soff);
        cp16(dstbase + TILEB + doff,   Alo + (size_t)(mbase+row)*K + soff);
        cp16(dstbase + 2*TILEB + doff, Bhi + (size_t)(nbase+row)*K + soff);
        cp16(dstbase + 3*TILEB + doff, Blo + (size_t)(nbase+row)*K + soff);
    };

    issue(sb, 0);
    CP_COMMIT();

    for (int it = 0; it < nch; it++) {
        if (it + 1 < nch) {
            issue(sb + ((it+1) & 1) * BUFB, (it+1) << 5);
            CP_COMMIT();
            CP_WAIT1();
        } else {
            CP_WAIT0();
        }
        __syncthreads();

        const uint32_t bufu = sb + (it & 1) * BUFB;

        #pragma unroll
        for (int ks = 0; ks < 32; ks += 16) {
            uint32_t ah[2][4], al[2][4], bh[4][2], bl[4][2];
            #pragma unroll
            for (int m = 0; m < 2; m++) {
                uint32_t ad = bufu + aoff + m*(16*80) + ks*2;
                LDSM4(ah[m][0], ah[m][1], ah[m][2], ah[m][3], ad);
                LDSM4(al[m][0], al[m][1], al[m][2], al[m][3], ad + TILEB);
            }
            #pragma unroll
            for (int n2 = 0; n2 < 2; n2++) {
                uint32_t bd = bufu + boff + n2*(16*80) + ks*2;
                uint32_t r0, r1, r2, r3;
                LDSM4(r0, r1, r2, r3, bd);
                bh[n2*2][0] = r0; bh[n2*2][1] = r1;
                bh[n2*2+1][0] = r2; bh[n2*2+1][1] = r3;
                LDSM4(r0, r1, r2, r3, bd + TILEB);
                bl[n2*2][0] = r0; bl[n2*2][1] = r1;
                bl[n2*2+1][0] = r2; bl[n2*2+1][1] = r3;
            }
            #pragma unroll
            for (int m = 0; m < 2; m++)
                #pragma unroll
                for (int n = 0; n < 4; n++) {
                    MMA_F32(acc[m][n], ah[m], bh[n]);
                    MMA_F16(acch[m][n], ah[m], bl[n]);
                    MMA_F16(acch[m][n], al[m], bh[n]);
                }
        }
        __syncthreads();
    }

    // epilogue: combine fp32 main + fp16 cross, stage through smem
    float* Cs = (float*)smem;   // [128][132]
    #pragma unroll
    for (int m = 0; m < 2; m++) {
        int r0 = warp_m*32 + m*16 + g;
        #pragma unroll
        for (int n = 0; n < 4; n++) {
            int col = warp_n*32 + n*8 + 2*q;
            __half2 p0 = *(__half2*)&acch[m][n][0];
            __half2 p1 = *(__half2*)&acch[m][n][1];
            Cs[r0*132 + col]       = acc[m][n][0] + __half2float(p0.x);
            Cs[r0*132 + col + 1]   = acc[m][n][1] + __half2float(p0.y);
            Cs[(r0+8)*132 + col]   = acc[m][n][2] + __half2float(p1.x);
            Cs[(r0+8)*132 + col+1] = acc[m][n][3] + __half2float(p1.y);
        }
    }
    __syncthreads();

    if (EPI == 1) {
        #pragma unroll
        for (int i = 0; i < 8; i++) {
            int u = tid + i*512;
            int row = u >> 5, c4 = (u & 31) * 4;
            int col = nbase + c4;
            float v0 = Cs[row*132 + c4 + 0] + bias[col];
            float v1 = Cs[row*132 + c4 + 1] + bias[col+1];
            float v2 = Cs[row*132 + c4 + 2] + bias[col+2];
            float v3 = Cs[row*132 + c4 + 3] + bias[col+3];
            v0 = fmaxf(v0, 0.f); v1 = fmaxf(v1, 0.f);
            v2 = fmaxf(v2, 0.f); v3 = fmaxf(v3, 0.f);
            float r0, r1, r2, r3;
            uint2 hi, lo;
            hi.x = pack2_hi(v0, v1, r0, r1);
            hi.y = pack2_hi(v2, v3, r2, r3);
            lo.x = pack2(r0, r1); lo.y = pack2(r2, r3);
            size_t off = (size_t)(mbase+row)*N + col;
            *(uint2*)(Chi + off) = hi;
            *(uint2*)(Clo + off) = lo;
        }
    } else if ((N & 3) == 0) {
        #pragma unroll
        for (int i = 0; i < 8; i++) {
            int u = tid + i*512;
            int row = u >> 5, c4 = (u & 31) * 4;
            int col = nbase + c4;
            float v0 = Cs[row*132 + c4 + 0];
            float v1 = Cs[row*132 + c4 + 1];
            float v2 = Cs[row*132 + c4 + 2];
            float v3 = Cs[row*132 + c4 + 3];
            if (bias) { v0 += bias[col]; v1 += bias[col+1]; v2 += bias[col+2]; v3 += bias[col+3]; }
            if (EPI == 2) {
                const float4 rv = *(const float4*)(res + (size_t)(mbase+row)*N + col);
                v0 += rv.x; v1 += rv.y; v2 += rv.z; v3 += rv.w;
            }
            *(float4*)(C + (size_t)(mbase+row)*N + col) = make_float4(v0, v1, v2, v3);
        }
    } else {
        #pragma unroll
        for (int i = 0; i < 8; i++) {
            int u = tid + i*512;
            int row = u >> 5, c4 = (u & 31) * 4;
            float* crow = C + (size_t)(mbase+row)*N;
            #pragma unroll
            for (int j = 0; j < 4; j++) {
                int col = nbase + c4 + j;
                if (col < N) {
                    float v = Cs[row*132 + c4 + j];
                    if (bias) v += bias[col];
                    if (EPI == 2) v += res[(size_t)(mbase+row)*N + col];
                    crow[col] = v;
                }
            }
        }
    }
}

// ---------------------------------------------------------------------------
// Tiled transpose + fp16 split: in [K,N] -> outhi/outlo [Npad,K], zero-pad
// ---------------------------------------------------------------------------
__global__ __launch_bounds__(256) void tp_kernel(
    const float* __restrict__ in,
    __half* __restrict__ outhi, __half* __restrict__ outlo,
    int K, int N, int Npad, size_t inStride, size_t outStride)
{
    __shared__ float t[32][33];
    const float* ip = in + blockIdx.z * inStride;
    __half* ohi = outhi + blockIdx.z * outStride;
    __half* olo = outlo + blockIdx.z * outStride;
    int n0 = blockIdx.x * 32, k0 = blockIdx.y * 32;
    int tx = threadIdx.x & 31, ty = threadIdx.x >> 5;
    #pragma unroll
    for (int j = ty; j < 32; j += 8) {
        int k = k0 + j, n = n0 + tx;
        t[j][tx] = (k < K && n < N) ? ip[(size_t)k * N + n] : 0.0f;
    }
    __syncthreads();
    #pragma unroll
    for (int j = ty; j < 32; j += 8) {
        int n = n0 + j, k = k0 + tx;
        if (n < Npad && k < K) {
            float v = t[tx][j];
            __half h = __float2half_rn(v);
            __half l = __float2half_rn(v - __half2float(h));
            ohi[(size_t)n * K + k] = h;
            olo[(size_t)n * K + k] = l;
        }
    }
}

// ---------------------------------------------------------------------------
// Elementwise fp16 split of a fp32 tensor (for LM-head input)
// ---------------------------------------------------------------------------
__global__ __launch_bounds__(256) void split_kernel(
    const float* __restrict__ x,
    __half* __restrict__ xhi, __half* __restrict__ xlo)
{
    size_t i = ((size_t)blockIdx.x * 256 + threadIdx.x) * 4;
    float4 v = *(const float4*)(x + i);
    float r0, r1, r2, r3;
    uint2 hi, lo;
    hi.x = pack2_hi(v.x, v.y, r0, r1);
    hi.y = pack2_hi(v.z, v.w, r2, r3);
    lo.x = pack2(r0, r1); lo.y = pack2(r2, r3);
    *(uint2*)(xhi + i) = hi;
    *(uint2*)(xlo + i) = lo;
}

// ---------------------------------------------------------------------------
// Embedding
// ---------------------------------------------------------------------------
__global__ __launch_bounds__(256) void embed_kernel(
    const int* __restrict__ idx, const float* __restrict__ tok,
    const float* __restrict__ pos, float* __restrict__ x)
{
    int row = blockIdx.x;
    int t   = row & (TT - 1);
    int id  = idx[row];
    const float4* tp = (const float4*)(tok + (size_t)id * DD);
    const float4* pp = (const float4*)(pos + (size_t)t  * DD);
    float4*       xp = (float4*)(x + (size_t)row * DD);
    int i = threadIdx.x;
    float4 a = tp[i], b = pp[i];
    a.x += b.x; a.y += b.y; a.z += b.z; a.w += b.w;
    xp[i] = a;
}

// ---------------------------------------------------------------------------
// LayerNorm -> fp16 hi/lo split output
// ---------------------------------------------------------------------------
__global__ __launch_bounds__(256) void ln_kernel(
    const float* __restrict__ x, const float* __restrict__ g,
    const float* __restrict__ b,
    __half* __restrict__ ohi, __half* __restrict__ olo)
{
    __shared__ float s1[256];
    __shared__ float s2[256];
    int row = blockIdx.x;
    int tid = threadIdx.x;
    float4 v = ((const float4*)(x + (size_t)row * DD))[tid];
    float s  = v.x + v.y + v.z + v.w;
    float ss = v.x*v.x + v.y*v.y + v.z*v.z + v.w*v.w;
    s1[tid] = s; s2[tid] = ss;
    __syncthreads();
    for (int o = 128; o > 0; o >>= 1) {
        if (tid < o) { s1[tid] += s1[tid+o]; s2[tid] += s2[tid+o]; }
        __syncthreads();
    }
    float mu   = s1[0] * (1.0f / DD);
    float var  = s2[0] * (1.0f / DD) - mu * mu;
    float rstd = rsqrtf(var + 1e-5f);
    float4 gv = ((const float4*)g)[tid];
    float4 bv = ((const float4*)b)[tid];
    float o0 = (v.x - mu) * rstd * gv.x + bv.x;
    float o1 = (v.y - mu) * rstd * gv.y + bv.y;
    float o2 = (v.z - mu) * rstd * gv.z + bv.z;
    float o3 = (v.w - mu) * rstd * gv.w + bv.w;
    float r0, r1, r2, r3;
    uint2 hi, lo;
    hi.x = pack2_hi(o0, o1, r0, r1);
    hi.y = pack2_hi(o2, o3, r2, r3);
    lo.x = pack2(r0, r1); lo.y = pack2(r2, r3);
    size_t off = (size_t)row * DD + tid * 4;
    *(uint2*)(ohi + off) = hi;
    *(uint2*)(olo + off) = lo;
}

// ---------------------------------------------------------------------------
// Fused causal attention: one thread per query, branchless 16-key score
// tiles with online softmax. Block = 128 threads/queries. Grid (B*H, T/128).
// ---------------------------------------------------------------------------
__global__ __launch_bounds__(128) void attn_kernel(
    const float* __restrict__ qkv,
    __half* __restrict__ yhi, __half* __restrict__ ylo)
{
    const int bh = blockIdx.x;
    const int b  = bh >> 4;
    const int h  = bh & (HH - 1);
    const int t  = blockIdx.y * 128 + threadIdx.x;
    const int row = b * TT + t;
    const int wid = threadIdx.x >> 5;

    __shared__ float Kt[64][HDIM];
    __shared__ float Vt[64][HDIM];

    float4 qv[16];
    {
        const float4* qp = (const float4*)(qkv + (size_t)row * (3*DD) + h * HDIM);
        #pragma unroll
        for (int i = 0; i < 16; i++) qv[i] = qp[i];
    }

    float4 acc[16];
    #pragma unroll
    for (int i = 0; i < 16; i++) acc[i] = make_float4(0.f, 0.f, 0.f, 0.f);
    float m = -1e30f, l = 0.0f;

    const int kmax = blockIdx.y * 128 + 127;
    const int warp_tmax = blockIdx.y * 128 + wid * 32 + 31;

    for (int k0 = 0; k0 <= kmax; k0 += 64) {
        {
            int r  = threadIdx.x >> 1;
            int c0 = (threadIdx.x & 1) * 32;
            const float* kp = qkv + (size_t)(b * TT + k0 + r) * (3*DD) + DD   + h * HDIM + c0;
            const float* vp = qkv + (size_t)(b * TT + k0 + r) * (3*DD) + 2*DD + h * HDIM + c0;
            #pragma unroll
            for (int i = 0; i < 8; i++) {
                *(float4*)&Kt[r][c0 + i*4] = *(const float4*)(kp + i*4);
                *(float4*)&Vt[r][c0 + i*4] = *(const float4*)(vp + i*4);
            }
        }
        __syncthreads();

        int jmaxw = warp_tmax - k0; if (jmaxw > 63) jmaxw = 63;
        int jme   = t - k0;         if (jme > 63)   jme = 63;

        for (int jt = 0; jt <= (jmaxw >> 4); jt++) {
            if (jt*16 <= jme) {
                float sc[16];
                #pragma unroll
                for (int jj = 0; jj < 16; jj++) {
                    int j = jt*16 + jj;
                    const float4* kr = (const float4*)&Kt[j][0];
                    float s = 0.0f;
                    #pragma unroll
                    for (int i = 0; i < 16; i++) {
                        float4 kk = kr[i];
                        s += qv[i].x*kk.x + qv[i].y*kk.y + qv[i].z*kk.z + qv[i].w*kk.w;
                    }
                    sc[jj] = (j <= jme) ? s * SCALE_ATT : -1e30f;
                }
                float tmax = sc[0];
                #pragma unroll
                for (int jj = 1; jj < 16; jj++) tmax = fmaxf(tmax, sc[jj]);
                float newm = fmaxf(m, tmax);
                float cor = __expf(m - newm);
                l *= cor;
                #pragma unroll
                for (int i = 0; i < 16; i++) {
                    acc[i].x *= cor; acc[i].y *= cor;
                    acc[i].z *= cor; acc[i].w *= cor;
                }
                #pragma unroll
                for (int jj = 0; jj < 16; jj++) {
                    float p = __expf(sc[jj] - newm);
                    l += p;
                    const float4* vr = (const float4*)&Vt[jt*16 + jj][0];
                    #pragma unroll
                    for (int i = 0; i < 16; i++) {
                        float4 vv = vr[i];
                        acc[i].x += p * vv.x; acc[i].y += p * vv.y;
                        acc[i].z += p * vv.z; acc[i].w += p * vv.w;
                    }
                }
                m = newm;
            }
        }
        __syncthreads();
    }

    float inv = 1.0f / l;
    size_t base = (size_t)row * DD + h * HDIM;
    #pragma unroll
    for (int i = 0; i < 16; i++) {
        float o0 = acc[i].x * inv, o1 = acc[i].y * inv;
        float o2 = acc[i].z * inv, o3 = acc[i].w * inv;
        float r0, r1, r2, r3;
        uint2 hi, lo;
        hi.x = pack2_hi(o0, o1, r0, r1);
        hi.y = pack2_hi(o2, o3, r2, r3);
        lo.x = pack2(r0, r1); lo.y = pack2(r2, r3);
        *(uint2*)(yhi + base + i*4) = hi;
        *(uint2*)(ylo + base + i*4) = lo;
    }
}

// ---------------------------------------------------------------------------
// NLL: single-pass online logsumexp
// ---------------------------------------------------------------------------
__global__ __launch_bounds__(256) void nll_kernel(
    const float* __restrict__ logits, const int* __restrict__ tgt,
    float* __restrict__ nll)
{
    __shared__ float rm[256];
    __shared__ float rs[256];
    int row = blockIdx.x;
    int tid = threadIdx.x;
    const float* lr = logits + (size_t)row * VV;

    float m = -3.4e38f, s = 0.0f;
    for (int i = tid; i < VV; i += 256) {
        float v = lr[i];
        if (v <= m) {
            s += __expf(v - m);
        } else {
            s = s * __expf(m - v) + 1.0f;
            m = v;
        }
    }
    rm[tid] = m; rs[tid] = s;
    __syncthreads();
    for (int o = 128; o > 0; o >>= 1) {
        if (tid < o) {
            float m2 = rm[tid + o], s2 = rs[tid + o];
            float M = fmaxf(rm[tid], m2);
            rs[tid] = rs[tid] * __expf(rm[tid] - M) + s2 * __expf(m2 - M);
            rm[tid] = M;
        }
        __syncthreads();
    }
    if (tid == 0) {
        float lse = rm[0] + logf(rs[0]);
        int tg = tgt[row];
        nll[row] = (tg != 0) ? (lse - lr[tg]) : 0.0f;
    }
}

__global__ __launch_bounds__(256) void loss_kernel(
    const float* __restrict__ nll, const int* __restrict__ tgt,
    float* __restrict__ out)
{
    __shared__ float s[256];
    __shared__ float c[256];
    int tid = threadIdx.x;
    float sv = 0.0f, cv = 0.0f;
    for (int i = tid; i < ROWS; i += 256) {
        sv += nll[i];
        cv += (tgt[i] != 0) ? 1.0f : 0.0f;
    }
    s[tid] = sv; c[tid] = cv; __syncthreads();
    for (int o = 128; o > 0; o >>= 1) {
        if (tid < o) { s[tid] += s[tid+o]; c[tid] += c[tid+o]; }
        __syncthreads();
    }
    if (tid == 0) out[0] = s[0] / fmaxf(c[0], 1.0f);
}

// ---------------------------------------------------------------------------
// Launcher
// ---------------------------------------------------------------------------
extern "C" void kernel_launch(void* const* d_in, const int* in_sizes, int n_in,
                              void* d_out, int out_size)
{
    const int*   idx   = (const int*)  d_in[0];
    const int*   tgt   = (const int*)  d_in[1];
    const float* tok   = (const float*)d_in[2];
    const float* pos   = (const float*)d_in[3];
    const float* ln1g  = (const float*)d_in[4];
    const float* ln1b  = (const float*)d_in[5];
    const float* wqkv  = (const float*)d_in[6];
    const float* bqkv  = (const float*)d_in[7];
    const float* wproj = (const float*)d_in[8];
    const float* bproj = (const float*)d_in[9];
    const float* ln2g  = (const float*)d_in[10];
    const float* ln2b  = (const float*)d_in[11];
    const float* w1    = (const float*)d_in[12];
    const float* b1    = (const float*)d_in[13];
    const float* w2    = (const float*)d_in[14];
    const float* b2    = (const float*)d_in[15];
    const float* lmw   = (const float*)d_in[16];

    float *px, *pqkv, *pnll;
    __half *phhi, *phlo, *pyhi, *pylo, *pmhi, *pmlo, *pxhi, *pxlo;
    __half *pwqkvhi, *pwqkvlo, *pwprojhi, *pwprojlo;
    __half *pw1hi, *pw1lo, *pw2hi, *pw2lo, *plmwhi, *plmwlo;
    cudaGetSymbolAddress((void**)&px,     g_x);
    cudaGetSymbolAddress((void**)&pqkv,   g_qkv);
    cudaGetSymbolAddress((void**)&pnll,   g_nll);
    cudaGetSymbolAddress((void**)&phhi,   g_hhi);
    cudaGetSymbolAddress((void**)&phlo,   g_hlo);
    cudaGetSymbolAddress((void**)&pyhi,   g_yhi);
    cudaGetSymbolAddress((void**)&pylo,   g_ylo);
    cudaGetSymbolAddress((void**)&pmhi,   g_mhi);
    cudaGetSymbolAddress((void**)&pmlo,   g_mlo);
    cudaGetSymbolAddress((void**)&pxhi,   g_xhi);
    cudaGetSymbolAddress((void**)&pxlo,   g_xlo);
    cudaGetSymbolAddress((void**)&pwqkvhi,  g_wqkvThi);
    cudaGetSymbolAddress((void**)&pwqkvlo,  g_wqkvTlo);
    cudaGetSymbolAddress((void**)&pwprojhi, g_wprojThi);
    cudaGetSymbolAddress((void**)&pwprojlo, g_wprojTlo);
    cudaGetSymbolAddress((void**)&pw1hi,  g_w1Thi);
    cudaGetSymbolAddress((void**)&pw1lo,  g_w1Tlo);
    cudaGetSymbolAddress((void**)&pw2hi,  g_w2Thi);
    cudaGetSymbolAddress((void**)&pw2lo,  g_w2Tlo);
    cudaGetSymbolAddress((void**)&plmwhi, g_lmwThi);
    cudaGetSymbolAddress((void**)&plmwlo, g_lmwTlo);

    cudaFuncSetAttribute((const void*)hgemm_kernel<0>,
                         cudaFuncAttributeMaxDynamicSharedMemorySize, SMEM_DYN);
    cudaFuncSetAttribute((const void*)hgemm_kernel<1>,
                         cudaFuncAttributeMaxDynamicSharedMemorySize, SMEM_DYN);
    cudaFuncSetAttribute((const void*)hgemm_kernel<2>,
                         cudaFuncAttributeMaxDynamicSharedMemorySize, SMEM_DYN);

    float* out = (float*)d_out;

    // weight transposes + fp16 split (graph-captured each launch)
    tp_kernel<<<dim3(3*DD/32, DD/32, LL), 256>>>(
        wqkv, pwqkvhi, pwqkvlo, DD, 3*DD, 3*DD, (size_t)DD*3*DD, (size_t)3*DD*DD);
    tp_kernel<<<dim3(DD/32, DD/32, LL), 256>>>(
        wproj, pwprojhi, pwprojlo, DD, DD, DD, (size_t)DD*DD, (size_t)DD*DD);
    tp_kernel<<<dim3(4*DD/32, DD/32, LL), 256>>>(
        w1, pw1hi, pw1lo, DD, 4*DD, 4*DD, (size_t)DD*4*DD, (size_t)4*DD*DD);
    tp_kernel<<<dim3(DD/32, 4*DD/32, LL), 256>>>(
        w2, pw2hi, pw2lo, 4*DD, DD, DD, (size_t)4*DD*DD, (size_t)DD*4*DD);
    tp_kernel<<<dim3(VPAD/32, DD/32, 1), 256>>>(
        lmw, plmwhi, plmwlo, DD, VV, VPAD, 0, 0);

    embed_kernel<<<ROWS, 256>>>(idx, tok, pos, px);

    for (int l = 0; l < LL; l++) {
        ln_kernel<<<ROWS, 256>>>(px, ln1g + (size_t)l*DD, ln1b + (size_t)l*DD, phhi, phlo);
        hgemm_kernel<0><<<dim3(ROWS/128, 3*DD/128), 512, SMEM_DYN>>>(
            ROWS, 3*DD, DD, phhi, phlo,
            pwqkvhi + (size_t)l*3*DD*DD, pwqkvlo + (size_t)l*3*DD*DD,
            bqkv + (size_t)l*3*DD, nullptr, pqkv, nullptr, nullptr);
        attn_kernel<<<dim3(BB*HH, TT/128), 128>>>(pqkv, pyhi, pylo);
        hgemm_kernel<2><<<dim3(ROWS/128, DD/128), 512, SMEM_DYN>>>(
            ROWS, DD, DD, pyhi, pylo,
            pwprojhi + (size_t)l*DD*DD, pwprojlo + (size_t)l*DD*DD,
            bproj + (size_t)l*DD, px, px, nullptr, nullptr);
        ln_kernel<<<ROWS, 256>>>(px, ln2g + (size_t)l*DD, ln2b + (size_t)l*DD, phhi, phlo);
        hgemm_kernel<1><<<dim3(ROWS/128, 4*DD/128), 512, SMEM_DYN>>>(
            ROWS, 4*DD, DD, phhi, phlo,
            pw1hi + (size_t)l*4*DD*DD, pw1lo + (size_t)l*4*DD*DD,
            b1 + (size_t)l*4*DD, nullptr, nullptr, pmhi, pmlo);
        hgemm_kernel<2><<<dim3(ROWS/128, DD/128), 512, SMEM_DYN>>>(
            ROWS, DD, 4*DD, pmhi, pmlo,
            pw2hi + (size_t)l*DD*4*DD, pw2lo + (size_t)l*DD*4*DD,
            b2 + (size_t)l*DD, px, px, nullptr, nullptr);
    }

    // split residual stream for LM head, then logits = x @ lm_w
    split_kernel<<<ROWS, 256>>>(px, pxhi, pxlo);
    hgemm_kernel<0><<<dim3(ROWS/128, VPAD/128), 512, SMEM_DYN>>>(
        ROWS, VV, DD, pxhi, pxlo, plmwhi, plmwlo,
        nullptr, nullptr, out, nullptr, nullptr);

    // loss
    nll_kernel<<<ROWS, 256>>>(out, tgt, pnll);
    size_t nlog = (size_t)ROWS * VV;
    if ((size_t)out_size > nlog) {
        loss_kernel<<<1, 256>>>(pnll, tgt, out + nlog);
    }
}

// round 10
// speedup vs baseline: 1.2535x; 1.2535x over previous
#include <cuda_runtime.h>
#include <cuda_fp16.h>
#include <math.h>
#include <stdint.h>

// Problem constants
#define BB 4
#define TT 1024
#define DD 1024
#define HH 16
#define HDIM 64
#define LL 8
#define VV 50257
#define VPAD 50304
#define ROWS (BB*TT)            // 4096
#define SCALE_ATT 0.07216878364870322f  // 1/sqrt(192)

// ---------------------------------------------------------------------------
// Scratch (static device globals; no runtime allocation)
// ---------------------------------------------------------------------------
__device__ float g_x   [ (size_t)ROWS * DD     ];   // residual stream (fp32)
__device__ float g_qkv [ (size_t)ROWS * 3 * DD ];   // qkv (fp32)
__device__ float g_nll [ ROWS ];
// plain fp16 activations (quantized once at each producer)
__device__ __half g_h  [ (size_t)ROWS * DD ];
__device__ __half g_y  [ (size_t)ROWS * DD ];
__device__ __half g_m  [ (size_t)ROWS * 4 * DD ];
__device__ __half g_xh [ (size_t)ROWS * DD ];
// fp16 hi/lo split transposed weights ([N,K] row-major; hi+lo exact to 2^-22)
__device__ __half g_wqkvThi [ (size_t)LL * 3*DD * DD ];
__device__ __half g_wqkvTlo [ (size_t)LL * 3*DD * DD ];
__device__ __half g_wprojThi[ (size_t)LL * DD * DD ];
__device__ __half g_wprojTlo[ (size_t)LL * DD * DD ];
__device__ __half g_w1Thi   [ (size_t)LL * 4*DD * DD ];
__device__ __half g_w1Tlo   [ (size_t)LL * 4*DD * DD ];
__device__ __half g_w2Thi   [ (size_t)LL * DD * 4*DD ];
__device__ __half g_w2Tlo   [ (size_t)LL * DD * 4*DD ];
__device__ __half g_lmwThi  [ (size_t)VPAD * DD ];
__device__ __half g_lmwTlo  [ (size_t)VPAD * DD ];

// ---------------------------------------------------------------------------
// helpers
// ---------------------------------------------------------------------------
__device__ __forceinline__ uint32_t smem_u32(const void* p) {
    uint32_t a;
    asm("{ .reg .u64 t; cvta.to.shared.u64 t, %1; cvt.u32.u64 %0, t; }"
        : "=r"(a) : "l"(p));
    return a;
}
__device__ __forceinline__ uint32_t pack2(float x, float y) {
    __half hx = __float2half_rn(x);
    __half hy = __float2half_rn(y);
    return (uint32_t)__half_as_ushort(hx) | ((uint32_t)__half_as_ushort(hy) << 16);
}

// fp16 inputs, fp32 accumulate (main term)
#define MMA_F32(d, a, b) \
    asm volatile("mma.sync.aligned.m16n8k16.row.col.f32.f16.f16.f32 " \
        "{%0,%1,%2,%3}, {%4,%5,%6,%7}, {%8,%9}, {%0,%1,%2,%3};" \
        : "+f"((d)[0]), "+f"((d)[1]), "+f"((d)[2]), "+f"((d)[3]) \
        : "r"((a)[0]), "r"((a)[1]), "r"((a)[2]), "r"((a)[3]), \
          "r"((b)[0]), "r"((b)[1]))

// fp16 inputs, fp16 accumulate (weight-lo correction term)
#define MMA_F16(d, a, b) \
    asm volatile("mma.sync.aligned.m16n8k16.row.col.f16.f16.f16.f16 " \
        "{%0,%1}, {%2,%3,%4,%5}, {%6,%7}, {%0,%1};" \
        : "+r"((d)[0]), "+r"((d)[1]) \
        : "r"((a)[0]), "r"((a)[1]), "r"((a)[2]), "r"((a)[3]), \
          "r"((b)[0]), "r"((b)[1]))

#define LDSM4(r0, r1, r2, r3, addr) \
    asm volatile("ldmatrix.sync.aligned.m8n8.x4.shared.b16 {%0,%1,%2,%3}, [%4];" \
        : "=r"(r0), "=r"(r1), "=r"(r2), "=r"(r3) : "r"(addr))

__device__ __forceinline__ void cp16(uint32_t d, const void* g) {
    asm volatile("cp.async.cg.shared.global [%0], [%1], 16;" :: "r"(d), "l"(g));
}
#define CP_COMMIT() asm volatile("cp.async.commit_group;" ::: "memory")
#define CP_WAIT0()  asm volatile("cp.async.wait_group 0;" ::: "memory")
#define CP_WAIT1()  asm volatile("cp.async.wait_group 1;" ::: "memory")

// ---------------------------------------------------------------------------
// Asymmetric-split tensor GEMM: C = A @ Bt^T.
// A plain fp16; B split hi/lo fp16. Per k-step: a*bh (fp32 acc) + a*bl
// (fp16 acc) = 2 MMAs. CTA tile 128x128, K-chunk 32, 2-stage cp.async,
// 512 threads, warp grid 4x4 (warp tile 32x32).
// EPI: 0=bias->f32, 1=bias+relu->fp16, 2=bias+residual->f32.
// smem per buffer: A | Bhi | Blo, each 128 rows x 80B.
// ---------------------------------------------------------------------------
#define TILEB 10240
#define BUFB  (3*TILEB)        // 30720
#define SMEM_DYN 67840         // max(2*BUFB=61440, Cs=128*132*4=67584)

template<int EPI>
__global__ __launch_bounds__(512) void hgemm_kernel(
    int M, int N, int K,
    const __half* __restrict__ A,
    const __half* __restrict__ Bhi, const __half* __restrict__ Blo,
    const float* __restrict__ bias, const float* __restrict__ res,
    float* __restrict__ C, __half* __restrict__ Ch)
{
    extern __shared__ __align__(128) char smem[];
    const uint32_t sb = smem_u32(smem);
    const int tid  = threadIdx.x;
    const int wid  = tid >> 5;
    const int lane = tid & 31;
    const int mbase = blockIdx.x * 128;
    const int nbase = blockIdx.y * 128;
    const int warp_m = wid & 3;
    const int warp_n = wid >> 2;
    const int g = lane >> 2;
    const int q = lane & 3;

    const uint32_t aoff = (uint32_t)(warp_m*32 + (lane & 15)) * 80
                        + ((lane >> 4) & 1) * 16;
    const uint32_t boff = TILEB
                        + (uint32_t)(warp_n*32 + (lane & 7) + ((lane >> 4) & 1)*8) * 80
                        + ((lane >> 3) & 1) * 16;

    float acc[2][4][4];
    uint32_t acch[2][4][2];
    #pragma unroll
    for (int m = 0; m < 2; m++)
        #pragma unroll
        for (int n = 0; n < 4; n++) {
            #pragma unroll
            for (int r = 0; r < 4; r++) acc[m][n][r] = 0.0f;
            acch[m][n][0] = 0u; acch[m][n][1] = 0u;
        }

    const int nch = K >> 5;

    auto issue = [&](uint32_t dstbase, int k0) {
        const int row = tid >> 2, seg = tid & 3;
        const uint32_t doff = (uint32_t)row*80 + seg*16;
        const int soff = k0 + seg*8;
        cp16(dstbase + doff,           A   + (size_t)(mbase+row)*K + soff);
        cp16(dstbase + TILEB + doff,   Bhi + (size_t)(nbase+row)*K + soff);
        cp16(dstbase + 2*TILEB + doff, Blo + (size_t)(nbase+row)*K + soff);
    };

    issue(sb, 0);
    CP_COMMIT();

    for (int it = 0; it < nch; it++) {
        if (it + 1 < nch) {
            issue(sb + ((it+1) & 1) * BUFB, (it+1) << 5);
            CP_COMMIT();
            CP_WAIT1();
        } else {
            CP_WAIT0();
        }
        __syncthreads();

        const uint32_t bufu = sb + (it & 1) * BUFB;

        #pragma unroll
        for (int ks = 0; ks < 32; ks += 16) {
            uint32_t ar[2][4], bh[4][2], bl[4][2];
            #pragma unroll
            for (int m = 0; m < 2; m++) {
                uint32_t ad = bufu + aoff + m*(16*80) + ks*2;
                LDSM4(ar[m][0], ar[m][1], ar[m][2], ar[m][3], ad);
            }
            #pragma unroll
            for (int n2 = 0; n2 < 2; n2++) {
                uint32_t bd = bufu + boff + n2*(16*80) + ks*2;
                uint32_t r0, r1, r2, r3;
                LDSM4(r0, r1, r2, r3, bd);
                bh[n2*2][0] = r0; bh[n2*2][1] = r1;
                bh[n2*2+1][0] = r2; bh[n2*2+1][1] = r3;
                LDSM4(r0, r1, r2, r3, bd + TILEB);
                bl[n2*2][0] = r0; bl[n2*2][1] = r1;
                bl[n2*2+1][0] = r2; bl[n2*2+1][1] = r3;
            }
            #pragma unroll
            for (int m = 0; m < 2; m++)
                #pragma unroll
                for (int n = 0; n < 4; n++) {
                    MMA_F32(acc[m][n], ar[m], bh[n]);
                    MMA_F16(acch[m][n], ar[m], bl[n]);
                }
        }
        __syncthreads();
    }

    // epilogue: combine fp32 main + fp16 correction, stage through smem
    float* Cs = (float*)smem;   // [128][132]
    #pragma unroll
    for (int m = 0; m < 2; m++) {
        int r0 = warp_m*32 + m*16 + g;
        #pragma unroll
        for (int n = 0; n < 4; n++) {
            int col = warp_n*32 + n*8 + 2*q;
            __half2 p0 = *(__half2*)&acch[m][n][0];
            __half2 p1 = *(__half2*)&acch[m][n][1];
            Cs[r0*132 + col]       = acc[m][n][0] + __half2float(p0.x);
            Cs[r0*132 + col + 1]   = acc[m][n][1] + __half2float(p0.y);
            Cs[(r0+8)*132 + col]   = acc[m][n][2] + __half2float(p1.x);
            Cs[(r0+8)*132 + col+1] = acc[m][n][3] + __half2float(p1.y);
        }
    }
    __syncthreads();

    if (EPI == 1) {
        #pragma unroll
        for (int i = 0; i < 8; i++) {
            int u = tid + i*512;
            int row = u >> 5, c4 = (u & 31) * 4;
            int col = nbase + c4;
            float v0 = Cs[row*132 + c4 + 0] + bias[col];
            float v1 = Cs[row*132 + c4 + 1] + bias[col+1];
            float v2 = Cs[row*132 + c4 + 2] + bias[col+2];
            float v3 = Cs[row*132 + c4 + 3] + bias[col+3];
            v0 = fmaxf(v0, 0.f); v1 = fmaxf(v1, 0.f);
            v2 = fmaxf(v2, 0.f); v3 = fmaxf(v3, 0.f);
            uint2 hv;
            hv.x = pack2(v0, v1);
            hv.y = pack2(v2, v3);
            *(uint2*)(Ch + (size_t)(mbase+row)*N + col) = hv;
        }
    } else if ((N & 3) == 0) {
        #pragma unroll
        for (int i = 0; i < 8; i++) {
            int u = tid + i*512;
            int row = u >> 5, c4 = (u & 31) * 4;
            int col = nbase + c4;
            float v0 = Cs[row*132 + c4 + 0];
            float v1 = Cs[row*132 + c4 + 1];
            float v2 = Cs[row*132 + c4 + 2];
            float v3 = Cs[row*132 + c4 + 3];
            if (bias) { v0 += bias[col]; v1 += bias[col+1]; v2 += bias[col+2]; v3 += bias[col+3]; }
            if (EPI == 2) {
                const float4 rv = *(const float4*)(res + (size_t)(mbase+row)*N + col);
                v0 += rv.x; v1 += rv.y; v2 += rv.z; v3 += rv.w;
            }
            *(float4*)(C + (size_t)(mbase+row)*N + col) = make_float4(v0, v1, v2, v3);
        }
    } else {
        #pragma unroll
        for (int i = 0; i < 8; i++) {
            int u = tid + i*512;
            int row = u >> 5, c4 = (u & 31) * 4;
            float* crow = C + (size_t)(mbase+row)*N;
            #pragma unroll
            for (int j = 0; j < 4; j++) {
                int col = nbase + c4 + j;
                if (col < N) {
                    float v = Cs[row*132 + c4 + j];
                    if (bias) v += bias[col];
                    if (EPI == 2) v += res[(size_t)(mbase+row)*N + col];
                    crow[col] = v;
                }
            }
        }
    }
}

// ---------------------------------------------------------------------------
// Tiled transpose + fp16 split (weights): in [K,N] -> hi/lo [Npad,K]
// ---------------------------------------------------------------------------
__global__ __launch_bounds__(256) void tp_kernel(
    const float* __restrict__ in,
    __half* __restrict__ outhi, __half* __restrict__ outlo,
    int K, int N, int Npad, size_t inStride, size_t outStride)
{
    __shared__ float t[32][33];
    const float* ip = in + blockIdx.z * inStride;
    __half* ohi = outhi + blockIdx.z * outStride;
    __half* olo = outlo + blockIdx.z * outStride;
    int n0 = blockIdx.x * 32, k0 = blockIdx.y * 32;
    int tx = threadIdx.x & 31, ty = threadIdx.x >> 5;
    #pragma unroll
    for (int j = ty; j < 32; j += 8) {
        int k = k0 + j, n = n0 + tx;
        t[j][tx] = (k < K && n < N) ? ip[(size_t)k * N + n] : 0.0f;
    }
    __syncthreads();
    #pragma unroll
    for (int j = ty; j < 32; j += 8) {
        int n = n0 + j, k = k0 + tx;
        if (n < Npad && k < K) {
            float v = t[tx][j];
            __half h = __float2half_rn(v);
            __half l = __float2half_rn(v - __half2float(h));
            ohi[(size_t)n * K + k] = h;
            olo[(size_t)n * K + k] = l;
        }
    }
}

// ---------------------------------------------------------------------------
// Elementwise fp16 quantize of a fp32 tensor (LM-head input)
// ---------------------------------------------------------------------------
__global__ __launch_bounds__(256) void tohalf_kernel(
    const float* __restrict__ x, __half* __restrict__ xh)
{
    size_t i = ((size_t)blockIdx.x * 256 + threadIdx.x) * 4;
    float4 v = *(const float4*)(x + i);
    uint2 hv;
    hv.x = pack2(v.x, v.y);
    hv.y = pack2(v.z, v.w);
    *(uint2*)(xh + i) = hv;
}

// ---------------------------------------------------------------------------
// Embedding
// ---------------------------------------------------------------------------
__global__ __launch_bounds__(256) void embed_kernel(
    const int* __restrict__ idx, const float* __restrict__ tok,
    const float* __restrict__ pos, float* __restrict__ x)
{
    int row = blockIdx.x;
    int t   = row & (TT - 1);
    int id  = idx[row];
    const float4* tp = (const float4*)(tok + (size_t)id * DD);
    const float4* pp = (const float4*)(pos + (size_t)t  * DD);
    float4*       xp = (float4*)(x + (size_t)row * DD);
    int i = threadIdx.x;
    float4 a = tp[i], b = pp[i];
    a.x += b.x; a.y += b.y; a.z += b.z; a.w += b.w;
    xp[i] = a;
}

// ---------------------------------------------------------------------------
// LayerNorm -> plain fp16 output
// ---------------------------------------------------------------------------
__global__ __launch_bounds__(256) void ln_kernel(
    const float* __restrict__ x, const float* __restrict__ g,
    const float* __restrict__ b, __half* __restrict__ oh)
{
    __shared__ float s1[256];
    __shared__ float s2[256];
    int row = blockIdx.x;
    int tid = threadIdx.x;
    float4 v = ((const float4*)(x + (size_t)row * DD))[tid];
    float s  = v.x + v.y + v.z + v.w;
    float ss = v.x*v.x + v.y*v.y + v.z*v.z + v.w*v.w;
    s1[tid] = s; s2[tid] = ss;
    __syncthreads();
    for (int o = 128; o > 0; o >>= 1) {
        if (tid < o) { s1[tid] += s1[tid+o]; s2[tid] += s2[tid+o]; }
        __syncthreads();
    }
    float mu   = s1[0] * (1.0f / DD);
    float var  = s2[0] * (1.0f / DD) - mu * mu;
    float rstd = rsqrtf(var + 1e-5f);
    float4 gv = ((const float4*)g)[tid];
    float4 bv = ((const float4*)b)[tid];
    float o0 = (v.x - mu) * rstd * gv.x + bv.x;
    float o1 = (v.y - mu) * rstd * gv.y + bv.y;
    float o2 = (v.z - mu) * rstd * gv.z + bv.z;
    float o3 = (v.w - mu) * rstd * gv.w + bv.w;
    uint2 hv;
    hv.x = pack2(o0, o1);
    hv.y = pack2(o2, o3);
    *(uint2*)(oh + (size_t)row * DD + tid * 4) = hv;
}

// ---------------------------------------------------------------------------
// Fused causal attention: one thread per query, branchless 16-key score
// tiles with online softmax. Block = 128 threads/queries. Grid (B*H, T/128).
// Output plain fp16.
// ---------------------------------------------------------------------------
__global__ __launch_bounds__(128) void attn_kernel(
    const float* __restrict__ qkv, __half* __restrict__ yh)
{
    const int bh = blockIdx.x;
    const int b  = bh >> 4;
    const int h  = bh & (HH - 1);
    const int t  = blockIdx.y * 128 + threadIdx.x;
    const int row = b * TT + t;
    const int wid = threadIdx.x >> 5;

    __shared__ float Kt[64][HDIM];
    __shared__ float Vt[64][HDIM];

    float4 qv[16];
    {
        const float4* qp = (const float4*)(qkv + (size_t)row * (3*DD) + h * HDIM);
        #pragma unroll
        for (int i = 0; i < 16; i++) qv[i] = qp[i];
    }

    float4 acc[16];
    #pragma unroll
    for (int i = 0; i < 16; i++) acc[i] = make_float4(0.f, 0.f, 0.f, 0.f);
    float m = -1e30f, l = 0.0f;

    const int kmax = blockIdx.y * 128 + 127;
    const int warp_tmax = blockIdx.y * 128 + wid * 32 + 31;

    for (int k0 = 0; k0 <= kmax; k0 += 64) {
        {
            int r  = threadIdx.x >> 1;
            int c0 = (threadIdx.x & 1) * 32;
            const float* kp = qkv + (size_t)(b * TT + k0 + r) * (3*DD) + DD   + h * HDIM + c0;
            const float* vp = qkv + (size_t)(b * TT + k0 + r) * (3*DD) + 2*DD + h * HDIM + c0;
            #pragma unroll
            for (int i = 0; i < 8; i++) {
                *(float4*)&Kt[r][c0 + i*4] = *(const float4*)(kp + i*4);
                *(float4*)&Vt[r][c0 + i*4] = *(const float4*)(vp + i*4);
            }
        }
        __syncthreads();

        int jmaxw = warp_tmax - k0; if (jmaxw > 63) jmaxw = 63;
        int jme   = t - k0;         if (jme > 63)   jme = 63;

        for (int jt = 0; jt <= (jmaxw >> 4); jt++) {
            if (jt*16 <= jme) {
                float sc[16];
                #pragma unroll
                for (int jj = 0; jj < 16; jj++) {
                    int j = jt*16 + jj;
                    const float4* kr = (const float4*)&Kt[j][0];
                    float s = 0.0f;
                    #pragma unroll
                    for (int i = 0; i < 16; i++) {
                        float4 kk = kr[i];
                        s += qv[i].x*kk.x + qv[i].y*kk.y + qv[i].z*kk.z + qv[i].w*kk.w;
                    }
                    sc[jj] = (j <= jme) ? s * SCALE_ATT : -1e30f;
                }
                float tmax = sc[0];
                #pragma unroll
                for (int jj = 1; jj < 16; jj++) tmax = fmaxf(tmax, sc[jj]);
                float newm = fmaxf(m, tmax);
                float cor = __expf(m - newm);
                l *= cor;
                #pragma unroll
                for (int i = 0; i < 16; i++) {
                    acc[i].x *= cor; acc[i].y *= cor;
                    acc[i].z *= cor; acc[i].w *= cor;
                }
                #pragma unroll
                for (int jj = 0; jj < 16; jj++) {
                    float p = __expf(sc[jj] - newm);
                    l += p;
                    const float4* vr = (const float4*)&Vt[jt*16 + jj][0];
                    #pragma unroll
                    for (int i = 0; i < 16; i++) {
                        float4 vv = vr[i];
                        acc[i].x += p * vv.x; acc[i].y += p * vv.y;
                        acc[i].z += p * vv.z; acc[i].w += p * vv.w;
                    }
                }
                m = newm;
            }
        }
        __syncthreads();
    }

    float inv = 1.0f / l;
    size_t base = (size_t)row * DD + h * HDIM;
    #pragma unroll
    for (int i = 0; i < 16; i++) {
        uint2 hv;
        hv.x = pack2(acc[i].x * inv, acc[i].y * inv);
        hv.y = pack2(acc[i].z * inv, acc[i].w * inv);
        *(uint2*)(yh + base + i*4) = hv;
    }
}

// ---------------------------------------------------------------------------
// NLL: single-pass online logsumexp
// ---------------------------------------------------------------------------
__global__ __launch_bounds__(256) void nll_kernel(
    const float* __restrict__ logits, const int* __restrict__ tgt,
    float* __restrict__ nll)
{
    __shared__ float rm[256];
    __shared__ float rs[256];
    int row = blockIdx.x;
    int tid = threadIdx.x;
    const float* lr = logits + (size_t)row * VV;

    float m = -3.4e38f, s = 0.0f;
    for (int i = tid; i < VV; i += 256) {
        float v = lr[i];
        if (v <= m) {
            s += __expf(v - m);
        } else {
            s = s * __expf(m - v) + 1.0f;
            m = v;
        }
    }
    rm[tid] = m; rs[tid] = s;
    __syncthreads();
    for (int o = 128; o > 0; o >>= 1) {
        if (tid < o) {
            float m2 = rm[tid + o], s2 = rs[tid + o];
            float M = fmaxf(rm[tid], m2);
            rs[tid] = rs[tid] * __expf(rm[tid] - M) + s2 * __expf(m2 - M);
            rm[tid] = M;
        }
        __syncthreads();
    }
    if (tid == 0) {
        float lse = rm[0] + logf(rs[0]);
        int tg = tgt[row];
        nll[row] = (tg != 0) ? (lse - lr[tg]) : 0.0f;
    }
}

__global__ __launch_bounds__(256) void loss_kernel(
    const float* __restrict__ nll, const int* __restrict__ tgt,
    float* __restrict__ out)
{
    __shared__ float s[256];
    __shared__ float c[256];
    int tid = threadIdx.x;
    float sv = 0.0f, cv = 0.0f;
    for (int i = tid; i < ROWS; i += 256) {
        sv += nll[i];
        cv += (tgt[i] != 0) ? 1.0f : 0.0f;
    }
    s[tid] = sv; c[tid] = cv; __syncthreads();
    for (int o = 128; o > 0; o >>= 1) {
        if (tid < o) { s[tid] += s[tid+o]; c[tid] += c[tid+o]; }
        __syncthreads();
    }
    if (tid == 0) out[0] = s[0] / fmaxf(c[0], 1.0f);
}

// ---------------------------------------------------------------------------
// Launcher
// ---------------------------------------------------------------------------
extern "C" void kernel_launch(void* const* d_in, const int* in_sizes, int n_in,
                              void* d_out, int out_size)
{
    const int*   idx   = (const int*)  d_in[0];
    const int*   tgt   = (const int*)  d_in[1];
    const float* tok   = (const float*)d_in[2];
    const float* pos   = (const float*)d_in[3];
    const float* ln1g  = (const float*)d_in[4];
    const float* ln1b  = (const float*)d_in[5];
    const float* wqkv  = (const float*)d_in[6];
    const float* bqkv  = (const float*)d_in[7];
    const float* wproj = (const float*)d_in[8];
    const float* bproj = (const float*)d_in[9];
    const float* ln2g  = (const float*)d_in[10];
    const float* ln2b  = (const float*)d_in[11];
    const float* w1    = (const float*)d_in[12];
    const float* b1    = (const float*)d_in[13];
    const float* w2    = (const float*)d_in[14];
    const float* b2    = (const float*)d_in[15];
    const float* lmw   = (const float*)d_in[16];

    float *px, *pqkv, *pnll;
    __half *ph, *py, *pm, *pxh;
    __half *pwqkvhi, *pwqkvlo, *pwprojhi, *pwprojlo;
    __half *pw1hi, *pw1lo, *pw2hi, *pw2lo, *plmwhi, *plmwlo;
    cudaGetSymbolAddress((void**)&px,     g_x);
    cudaGetSymbolAddress((void**)&pqkv,   g_qkv);
    cudaGetSymbolAddress((void**)&pnll,   g_nll);
    cudaGetSymbolAddress((void**)&ph,     g_h);
    cudaGetSymbolAddress((void**)&py,     g_y);
    cudaGetSymbolAddress((void**)&pm,     g_m);
    cudaGetSymbolAddress((void**)&pxh,    g_xh);
    cudaGetSymbolAddress((void**)&pwqkvhi,  g_wqkvThi);
    cudaGetSymbolAddress((void**)&pwqkvlo,  g_wqkvTlo);
    cudaGetSymbolAddress((void**)&pwprojhi, g_wprojThi);
    cudaGetSymbolAddress((void**)&pwprojlo, g_wprojTlo);
    cudaGetSymbolAddress((void**)&pw1hi,  g_w1Thi);
    cudaGetSymbolAddress((void**)&pw1lo,  g_w1Tlo);
    cudaGetSymbolAddress((void**)&pw2hi,  g_w2Thi);
    cudaGetSymbolAddress((void**)&pw2lo,  g_w2Tlo);
    cudaGetSymbolAddress((void**)&plmwhi, g_lmwThi);
    cudaGetSymbolAddress((void**)&plmwlo, g_lmwTlo);

    cudaFuncSetAttribute((const void*)hgemm_kernel<0>,
                         cudaFuncAttributeMaxDynamicSharedMemorySize, SMEM_DYN);
    cudaFuncSetAttribute((const void*)hgemm_kernel<1>,
                         cudaFuncAttributeMaxDynamicSharedMemorySize, SMEM_DYN);
    cudaFuncSetAttribute((const void*)hgemm_kernel<2>,
                         cudaFuncAttributeMaxDynamicSharedMemorySize, SMEM_DYN);

    float* out = (float*)d_out;

    // weight transposes + fp16 split (graph-captured each launch)
    tp_kernel<<<dim3(3*DD/32, DD/32, LL), 256>>>(
        wqkv, pwqkvhi, pwqkvlo, DD, 3*DD, 3*DD, (size_t)DD*3*DD, (size_t)3*DD*DD);
    tp_kernel<<<dim3(DD/32, DD/32, LL), 256>>>(
        wproj, pwprojhi, pwprojlo, DD, DD, DD, (size_t)DD*DD, (size_t)DD*DD);
    tp_kernel<<<dim3(4*DD/32, DD/32, LL), 256>>>(
        w1, pw1hi, pw1lo, DD, 4*DD, 4*DD, (size_t)DD*4*DD, (size_t)4*DD*DD);
    tp_kernel<<<dim3(DD/32, 4*DD/32, LL), 256>>>(
        w2, pw2hi, pw2lo, 4*DD, DD, DD, (size_t)4*DD*DD, (size_t)DD*4*DD);
    tp_kernel<<<dim3(VPAD/32, DD/32, 1), 256>>>(
        lmw, plmwhi, plmwlo, DD, VV, VPAD, 0, 0);

    embed_kernel<<<ROWS, 256>>>(idx, tok, pos, px);

    for (int l = 0; l < LL; l++) {
        ln_kernel<<<ROWS, 256>>>(px, ln1g + (size_t)l*DD, ln1b + (size_t)l*DD, ph);
        hgemm_kernel<0><<<dim3(ROWS/128, 3*DD/128), 512, SMEM_DYN>>>(
            ROWS, 3*DD, DD, ph,
            pwqkvhi + (size_t)l*3*DD*DD, pwqkvlo + (size_t)l*3*DD*DD,
            bqkv + (size_t)l*3*DD, nullptr, pqkv, nullptr);
        attn_kernel<<<dim3(BB*HH, TT/128), 128>>>(pqkv, py);
        hgemm_kernel<2><<<dim3(ROWS/128, DD/128), 512, SMEM_DYN>>>(
            ROWS, DD, DD, py,
            pwprojhi + (size_t)l*DD*DD, pwprojlo + (size_t)l*DD*DD,
            bproj + (size_t)l*DD, px, px, nullptr);
        ln_kernel<<<ROWS, 256>>>(px, ln2g + (size_t)l*DD, ln2b + (size_t)l*DD, ph);
        hgemm_kernel<1><<<dim3(ROWS/128, 4*DD/128), 512, SMEM_DYN>>>(
            ROWS, 4*DD, DD, ph,
            pw1hi + (size_t)l*4*DD*DD, pw1lo + (size_t)l*4*DD*DD,
            b1 + (size_t)l*4*DD, nullptr, nullptr, pm);
        hgemm_kernel<2><<<dim3(ROWS/128, DD/128), 512, SMEM_DYN>>>(
            ROWS, DD, 4*DD, pm,
            pw2hi + (size_t)l*DD*4*DD, pw2lo + (size_t)l*DD*4*DD,
            b2 + (size_t)l*DD, px, px, nullptr);
    }

    // quantize residual stream for LM head, then logits = x @ lm_w
    tohalf_kernel<<<ROWS, 256>>>(px, pxh);
    hgemm_kernel<0><<<dim3(ROWS/128, VPAD/128), 512, SMEM_DYN>>>(
        ROWS, VV, DD, pxh, plmwhi, plmwlo,
        nullptr, nullptr, out, nullptr);

    // loss
    nll_kernel<<<ROWS, 256>>>(out, tgt, pnll);
    size_t nlog = (size_t)ROWS * VV;
    if ((size_t)out_size > nlog) {
        loss_kernel<<<1, 256>>>(pnll, tgt, out + nlog);
    }
}

// round 11
// speedup vs baseline: 1.7121x; 1.3658x over previous
#include <cuda_runtime.h>
#include <cuda_fp16.h>
#include <math.h>
#include <stdint.h>

// Problem constants
#define BB 4
#define TT 1024
#define DD 1024
#define HH 16
#define HDIM 64
#define LL 8
#define VV 50257
#define VPAD 50304
#define ROWS (BB*TT)            // 4096
#define SCALE_ATT 0.07216878364870322f  // 1/sqrt(192)

// ---------------------------------------------------------------------------
// Scratch (static device globals; no runtime allocation)
// ---------------------------------------------------------------------------
__device__ float g_x   [ (size_t)ROWS * DD     ];   // residual stream (fp32)
__device__ float g_qkv [ (size_t)ROWS * 3 * DD ];   // qkv (fp32)
__device__ float g_nll [ ROWS ];
// plain fp16 activations
__device__ __half g_h  [ (size_t)ROWS * DD ];
__device__ __half g_y  [ (size_t)ROWS * DD ];
__device__ __half g_m  [ (size_t)ROWS * 4 * DD ];
__device__ __half g_xh [ (size_t)ROWS * DD ];
// fp16 hi/lo split transposed weights ([N,K] row-major; hi+lo exact to 2^-22)
__device__ __half g_wqkvThi [ (size_t)LL * 3*DD * DD ];
__device__ __half g_wqkvTlo [ (size_t)LL * 3*DD * DD ];
__device__ __half g_wprojThi[ (size_t)LL * DD * DD ];
__device__ __half g_wprojTlo[ (size_t)LL * DD * DD ];
__device__ __half g_w1Thi   [ (size_t)LL * 4*DD * DD ];
__device__ __half g_w1Tlo   [ (size_t)LL * 4*DD * DD ];
__device__ __half g_w2Thi   [ (size_t)LL * DD * 4*DD ];
__device__ __half g_w2Tlo   [ (size_t)LL * DD * 4*DD ];
__device__ __half g_lmwThi  [ (size_t)VPAD * DD ];
__device__ __half g_lmwTlo  [ (size_t)VPAD * DD ];

// ---------------------------------------------------------------------------
// helpers
// ---------------------------------------------------------------------------
__device__ __forceinline__ uint32_t smem_u32(const void* p) {
    uint32_t a;
    asm("{ .reg .u64 t; cvta.to.shared.u64 t, %1; cvt.u32.u64 %0, t; }"
        : "=r"(a) : "l"(p));
    return a;
}
__device__ __forceinline__ uint32_t pack2(float x, float y) {
    __half hx = __float2half_rn(x);
    __half hy = __float2half_rn(y);
    return (uint32_t)__half_as_ushort(hx) | ((uint32_t)__half_as_ushort(hy) << 16);
}

#define MMA_F32(d, a, b) \
    asm volatile("mma.sync.aligned.m16n8k16.row.col.f32.f16.f16.f32 " \
        "{%0,%1,%2,%3}, {%4,%5,%6,%7}, {%8,%9}, {%0,%1,%2,%3};" \
        : "+f"((d)[0]), "+f"((d)[1]), "+f"((d)[2]), "+f"((d)[3]) \
        : "r"((a)[0]), "r"((a)[1]), "r"((a)[2]), "r"((a)[3]), \
          "r"((b)[0]), "r"((b)[1]))

#define MMA_F16(d, a, b) \
    asm volatile("mma.sync.aligned.m16n8k16.row.col.f16.f16.f16.f16 " \
        "{%0,%1}, {%2,%3,%4,%5}, {%6,%7}, {%0,%1};" \
        : "+r"((d)[0]), "+r"((d)[1]) \
        : "r"((a)[0]), "r"((a)[1]), "r"((a)[2]), "r"((a)[3]), \
          "r"((b)[0]), "r"((b)[1]))

#define LDSM4(r0, r1, r2, r3, addr) \
    asm volatile("ldmatrix.sync.aligned.m8n8.x4.shared.b16 {%0,%1,%2,%3}, [%4];" \
        : "=r"(r0), "=r"(r1), "=r"(r2), "=r"(r3) : "r"(addr))

#define LDSM4T(r0, r1, r2, r3, addr) \
    asm volatile("ldmatrix.sync.aligned.m8n8.x4.trans.shared.b16 {%0,%1,%2,%3}, [%4];" \
        : "=r"(r0), "=r"(r1), "=r"(r2), "=r"(r3) : "r"(addr))

__device__ __forceinline__ void cp16(uint32_t d, const void* g) {
    asm volatile("cp.async.cg.shared.global [%0], [%1], 16;" :: "r"(d), "l"(g));
}
#define CP_COMMIT() asm volatile("cp.async.commit_group;" ::: "memory")
#define CP_WAIT0()  asm volatile("cp.async.wait_group 0;" ::: "memory")
#define CP_WAIT1()  asm volatile("cp.async.wait_group 1;" ::: "memory")

// ---------------------------------------------------------------------------
// Asymmetric-split tensor GEMM (unchanged from R10)
// ---------------------------------------------------------------------------
#define TILEB 10240
#define BUFB  (3*TILEB)        // 30720
#define SMEM_DYN 67840

template<int EPI>
__global__ __launch_bounds__(512) void hgemm_kernel(
    int M, int N, int K,
    const __half* __restrict__ A,
    const __half* __restrict__ Bhi, const __half* __restrict__ Blo,
    const float* __restrict__ bias, const float* __restrict__ res,
    float* __restrict__ C, __half* __restrict__ Ch)
{
    extern __shared__ __align__(128) char smem[];
    const uint32_t sb = smem_u32(smem);
    const int tid  = threadIdx.x;
    const int wid  = tid >> 5;
    const int lane = tid & 31;
    const int mbase = blockIdx.x * 128;
    const int nbase = blockIdx.y * 128;
    const int warp_m = wid & 3;
    const int warp_n = wid >> 2;
    const int g = lane >> 2;
    const int q = lane & 3;

    const uint32_t aoff = (uint32_t)(warp_m*32 + (lane & 15)) * 80
                        + ((lane >> 4) & 1) * 16;
    const uint32_t boff = TILEB
                        + (uint32_t)(warp_n*32 + (lane & 7) + ((lane >> 4) & 1)*8) * 80
                        + ((lane >> 3) & 1) * 16;

    float acc[2][4][4];
    uint32_t acch[2][4][2];
    #pragma unroll
    for (int m = 0; m < 2; m++)
        #pragma unroll
        for (int n = 0; n < 4; n++) {
            #pragma unroll
            for (int r = 0; r < 4; r++) acc[m][n][r] = 0.0f;
            acch[m][n][0] = 0u; acch[m][n][1] = 0u;
        }

    const int nch = K >> 5;

    auto issue = [&](uint32_t dstbase, int k0) {
        const int row = tid >> 2, seg = tid & 3;
        const uint32_t doff = (uint32_t)row*80 + seg*16;
        const int soff = k0 + seg*8;
        cp16(dstbase + doff,           A   + (size_t)(mbase+row)*K + soff);
        cp16(dstbase + TILEB + doff,   Bhi + (size_t)(nbase+row)*K + soff);
        cp16(dstbase + 2*TILEB + doff, Blo + (size_t)(nbase+row)*K + soff);
    };

    issue(sb, 0);
    CP_COMMIT();

    for (int it = 0; it < nch; it++) {
        if (it + 1 < nch) {
            issue(sb + ((it+1) & 1) * BUFB, (it+1) << 5);
            CP_COMMIT();
            CP_WAIT1();
        } else {
            CP_WAIT0();
        }
        __syncthreads();

        const uint32_t bufu = sb + (it & 1) * BUFB;

        #pragma unroll
        for (int ks = 0; ks < 32; ks += 16) {
            uint32_t ar[2][4], bh[4][2], bl[4][2];
            #pragma unroll
            for (int m = 0; m < 2; m++) {
                uint32_t ad = bufu + aoff + m*(16*80) + ks*2;
                LDSM4(ar[m][0], ar[m][1], ar[m][2], ar[m][3], ad);
            }
            #pragma unroll
            for (int n2 = 0; n2 < 2; n2++) {
                uint32_t bd = bufu + boff + n2*(16*80) + ks*2;
                uint32_t r0, r1, r2, r3;
                LDSM4(r0, r1, r2, r3, bd);
                bh[n2*2][0] = r0; bh[n2*2][1] = r1;
                bh[n2*2+1][0] = r2; bh[n2*2+1][1] = r3;
                LDSM4(r0, r1, r2, r3, bd + TILEB);
                bl[n2*2][0] = r0; bl[n2*2][1] = r1;
                bl[n2*2+1][0] = r2; bl[n2*2+1][1] = r3;
            }
            #pragma unroll
            for (int m = 0; m < 2; m++)
                #pragma unroll
                for (int n = 0; n < 4; n++) {
                    MMA_F32(acc[m][n], ar[m], bh[n]);
                    MMA_F16(acch[m][n], ar[m], bl[n]);
                }
        }
        __syncthreads();
    }

    float* Cs = (float*)smem;   // [128][132]
    #pragma unroll
    for (int m = 0; m < 2; m++) {
        int r0 = warp_m*32 + m*16 + g;
        #pragma unroll
        for (int n = 0; n < 4; n++) {
            int col = warp_n*32 + n*8 + 2*q;
            __half2 p0 = *(__half2*)&acch[m][n][0];
            __half2 p1 = *(__half2*)&acch[m][n][1];
            Cs[r0*132 + col]       = acc[m][n][0] + __half2float(p0.x);
            Cs[r0*132 + col + 1]   = acc[m][n][1] + __half2float(p0.y);
            Cs[(r0+8)*132 + col]   = acc[m][n][2] + __half2float(p1.x);
            Cs[(r0+8)*132 + col+1] = acc[m][n][3] + __half2float(p1.y);
        }
    }
    __syncthreads();

    if (EPI == 1) {
        #pragma unroll
        for (int i = 0; i < 8; i++) {
            int u = tid + i*512;
            int row = u >> 5, c4 = (u & 31) * 4;
            int col = nbase + c4;
            float v0 = Cs[row*132 + c4 + 0] + bias[col];
            float v1 = Cs[row*132 + c4 + 1] + bias[col+1];
            float v2 = Cs[row*132 + c4 + 2] + bias[col+2];
            float v3 = Cs[row*132 + c4 + 3] + bias[col+3];
            v0 = fmaxf(v0, 0.f); v1 = fmaxf(v1, 0.f);
            v2 = fmaxf(v2, 0.f); v3 = fmaxf(v3, 0.f);
            uint2 hv;
            hv.x = pack2(v0, v1);
            hv.y = pack2(v2, v3);
            *(uint2*)(Ch + (size_t)(mbase+row)*N + col) = hv;
        }
    } else if ((N & 3) == 0) {
        #pragma unroll
        for (int i = 0; i < 8; i++) {
            int u = tid + i*512;
            int row = u >> 5, c4 = (u & 31) * 4;
            int col = nbase + c4;
            float v0 = Cs[row*132 + c4 + 0];
            float v1 = Cs[row*132 + c4 + 1];
            float v2 = Cs[row*132 + c4 + 2];
            float v3 = Cs[row*132 + c4 + 3];
            if (bias) { v0 += bias[col]; v1 += bias[col+1]; v2 += bias[col+2]; v3 += bias[col+3]; }
            if (EPI == 2) {
                const float4 rv = *(const float4*)(res + (size_t)(mbase+row)*N + col);
                v0 += rv.x; v1 += rv.y; v2 += rv.z; v3 += rv.w;
            }
            *(float4*)(C + (size_t)(mbase+row)*N + col) = make_float4(v0, v1, v2, v3);
        }
    } else {
        #pragma unroll
        for (int i = 0; i < 8; i++) {
            int u = tid + i*512;
            int row = u >> 5, c4 = (u & 31) * 4;
            float* crow = C + (size_t)(mbase+row)*N;
            #pragma unroll
            for (int j = 0; j < 4; j++) {
                int col = nbase + c4 + j;
                if (col < N) {
                    float v = Cs[row*132 + c4 + j];
                    if (bias) v += bias[col];
                    if (EPI == 2) v += res[(size_t)(mbase+row)*N + col];
                    crow[col] = v;
                }
            }
        }
    }
}

// ---------------------------------------------------------------------------
// Tiled transpose + fp16 split (weights): in [K,N] -> hi/lo [Npad,K]
// ---------------------------------------------------------------------------
__global__ __launch_bounds__(256) void tp_kernel(
    const float* __restrict__ in,
    __half* __restrict__ outhi, __half* __restrict__ outlo,
    int K, int N, int Npad, size_t inStride, size_t outStride)
{
    __shared__ float t[32][33];
    const float* ip = in + blockIdx.z * inStride;
    __half* ohi = outhi + blockIdx.z * outStride;
    __half* olo = outlo + blockIdx.z * outStride;
    int n0 = blockIdx.x * 32, k0 = blockIdx.y * 32;
    int tx = threadIdx.x & 31, ty = threadIdx.x >> 5;
    #pragma unroll
    for (int j = ty; j < 32; j += 8) {
        int k = k0 + j, n = n0 + tx;
        t[j][tx] = (k < K && n < N) ? ip[(size_t)k * N + n] : 0.0f;
    }
    __syncthreads();
    #pragma unroll
    for (int j = ty; j < 32; j += 8) {
        int n = n0 + j, k = k0 + tx;
        if (n < Npad && k < K) {
            float v = t[tx][j];
            __half h = __float2half_rn(v);
            __half l = __float2half_rn(v - __half2float(h));
            ohi[(size_t)n * K + k] = h;
            olo[(size_t)n * K + k] = l;
        }
    }
}

// ---------------------------------------------------------------------------
// Elementwise fp16 quantize (LM-head input)
// ---------------------------------------------------------------------------
__global__ __launch_bounds__(256) void tohalf_kernel(
    const float* __restrict__ x, __half* __restrict__ xh)
{
    size_t i = ((size_t)blockIdx.x * 256 + threadIdx.x) * 4;
    float4 v = *(const float4*)(x + i);
    uint2 hv;
    hv.x = pack2(v.x, v.y);
    hv.y = pack2(v.z, v.w);
    *(uint2*)(xh + i) = hv;
}

// ---------------------------------------------------------------------------
// Embedding
// ---------------------------------------------------------------------------
__global__ __launch_bounds__(256) void embed_kernel(
    const int* __restrict__ idx, const float* __restrict__ tok,
    const float* __restrict__ pos, float* __restrict__ x)
{
    int row = blockIdx.x;
    int t   = row & (TT - 1);
    int id  = idx[row];
    const float4* tp = (const float4*)(tok + (size_t)id * DD);
    const float4* pp = (const float4*)(pos + (size_t)t  * DD);
    float4*       xp = (float4*)(x + (size_t)row * DD);
    int i = threadIdx.x;
    float4 a = tp[i], b = pp[i];
    a.x += b.x; a.y += b.y; a.z += b.z; a.w += b.w;
    xp[i] = a;
}

// ---------------------------------------------------------------------------
// LayerNorm -> plain fp16 output
// ---------------------------------------------------------------------------
__global__ __launch_bounds__(256) void ln_kernel(
    const float* __restrict__ x, const float* __restrict__ g,
    const float* __restrict__ b, __half* __restrict__ oh)
{
    __shared__ float s1[256];
    __shared__ float s2[256];
    int row = blockIdx.x;
    int tid = threadIdx.x;
    float4 v = ((const float4*)(x + (size_t)row * DD))[tid];
    float s  = v.x + v.y + v.z + v.w;
    float ss = v.x*v.x + v.y*v.y + v.z*v.z + v.w*v.w;
    s1[tid] = s; s2[tid] = ss;
    __syncthreads();
    for (int o = 128; o > 0; o >>= 1) {
        if (tid < o) { s1[tid] += s1[tid+o]; s2[tid] += s2[tid+o]; }
        __syncthreads();
    }
    float mu   = s1[0] * (1.0f / DD);
    float var  = s2[0] * (1.0f / DD) - mu * mu;
    float rstd = rsqrtf(var + 1e-5f);
    float4 gv = ((const float4*)g)[tid];
    float4 bv = ((const float4*)b)[tid];
    float o0 = (v.x - mu) * rstd * gv.x + bv.x;
    float o1 = (v.y - mu) * rstd * gv.y + bv.y;
    float o2 = (v.z - mu) * rstd * gv.z + bv.z;
    float o3 = (v.w - mu) * rstd * gv.w + bv.w;
    uint2 hv;
    hv.x = pack2(o0, o1);
    hv.y = pack2(o2, o3);
    *(uint2*)(oh + (size_t)row * DD + tid * 4) = hv;
}

// ---------------------------------------------------------------------------
// Tensor-core flash attention. Block = 128 threads (4 warps) handles one
// (b,h) and a 64-query tile. Warp w owns 16 query rows. K tiles of 64 keys:
// S = Q@K^T (fp16 in, fp32 acc), online softmax in C-frag layout, P packed
// to A-frags (layout identity), O += P@V with V B-frags via ldmatrix.trans.
// smem: Q | K | V tiles, 64 rows x 144B pitch (conflict-free ldmatrix).
// Grid: (B*H, T/64).
// ---------------------------------------------------------------------------
#define APITCH 144

__global__ __launch_bounds__(128) void attn_kernel(
    const float* __restrict__ qkv, __half* __restrict__ yh)
{
    __shared__ __align__(16) char sm[3 * 64 * APITCH];   // 27648 B
    char* Qs = sm;
    char* Ks = sm + 64*APITCH;
    char* Vs = sm + 2*64*APITCH;

    const int tid  = threadIdx.x;
    const int wid  = tid >> 5;
    const int lane = tid & 31;
    const int g = lane >> 2;
    const int q = lane & 3;
    const int bh = blockIdx.x;
    const int b  = bh >> 4;
    const int h  = bh & (HH - 1);
    const int qbase = blockIdx.y * 64;

    // load Q tile -> fp16 smem
    {
        int row = tid >> 1;
        int c0  = (tid & 1) * 32;
        const float* src = qkv + (size_t)(b*TT + qbase + row)*(3*DD) + h*HDIM + c0;
        char* dp = Qs + row*APITCH + c0*2;
        #pragma unroll
        for (int j = 0; j < 4; j++) {
            float4 v0 = *(const float4*)(src + j*8);
            float4 v1 = *(const float4*)(src + j*8 + 4);
            uint4 o;
            o.x = pack2(v0.x, v0.y); o.y = pack2(v0.z, v0.w);
            o.z = pack2(v1.x, v1.y); o.w = pack2(v1.z, v1.w);
            *(uint4*)(dp + j*16) = o;
        }
    }
    __syncthreads();

    // Q A-frags (held in registers for whole kernel)
    uint32_t qa[4][4];
    {
        uint32_t qaddr = smem_u32(Qs) + (uint32_t)(wid*16 + (lane & 15))*APITCH
                       + ((lane >> 4) & 1) * 16;
        #pragma unroll
        for (int c = 0; c < 4; c++)
            LDSM4(qa[c][0], qa[c][1], qa[c][2], qa[c][3], qaddr + c*32);
    }

    const int qrow0 = qbase + wid*16 + g;
    const int qrow1 = qrow0 + 8;

    float m0 = -1e30f, m1 = -1e30f, l0 = 0.0f, l1 = 0.0f;
    float oacc[8][4];
    #pragma unroll
    for (int n = 0; n < 8; n++)
        #pragma unroll
        for (int r = 0; r < 4; r++) oacc[n][r] = 0.0f;

    const uint32_t kfr = smem_u32(Ks) + (uint32_t)((lane & 7) + ((lane >> 4) & 1)*8)*APITCH
                       + ((lane >> 3) & 1) * 16;
    const uint32_t vfr = smem_u32(Vs) + (uint32_t)((lane & 7) + ((lane >> 3) & 1)*8)*APITCH
                       + ((lane >> 4) & 1) * 16;

    const int ntiles = blockIdx.y + 1;
    for (int kt = 0; kt < ntiles; kt++) {
        const int kbase = kt * 64;
        __syncthreads();   // previous tile's frags consumed
        {
            int row = tid >> 1;
            int c0  = (tid & 1) * 32;
            const float* sk = qkv + (size_t)(b*TT + kbase + row)*(3*DD) + DD   + h*HDIM + c0;
            const float* sv = qkv + (size_t)(b*TT + kbase + row)*(3*DD) + 2*DD + h*HDIM + c0;
            char* dk = Ks + row*APITCH + c0*2;
            char* dv = Vs + row*APITCH + c0*2;
            #pragma unroll
            for (int j = 0; j < 4; j++) {
                float4 v0 = *(const float4*)(sk + j*8);
                float4 v1 = *(const float4*)(sk + j*8 + 4);
                uint4 o;
                o.x = pack2(v0.x, v0.y); o.y = pack2(v0.z, v0.w);
                o.z = pack2(v1.x, v1.y); o.w = pack2(v1.z, v1.w);
                *(uint4*)(dk + j*16) = o;
                v0 = *(const float4*)(sv + j*8);
                v1 = *(const float4*)(sv + j*8 + 4);
                o.x = pack2(v0.x, v0.y); o.y = pack2(v0.z, v0.w);
                o.z = pack2(v1.x, v1.y); o.w = pack2(v1.z, v1.w);
                *(uint4*)(dv + j*16) = o;
            }
        }
        __syncthreads();

        // S = Q @ K^T  (8 n-tiles of 8 keys)
        float s[8][4];
        #pragma unroll
        for (int n = 0; n < 8; n++)
            #pragma unroll
            for (int r = 0; r < 4; r++) s[n][r] = 0.0f;
        #pragma unroll
        for (int kc = 0; kc < 4; kc++) {
            #pragma unroll
            for (int n2 = 0; n2 < 4; n2++) {
                uint32_t r0, r1, r2, r3;
                LDSM4(r0, r1, r2, r3, kfr + (uint32_t)n2*(16*APITCH) + kc*32);
                uint32_t kb0[2] = {r0, r1};
                uint32_t kb1[2] = {r2, r3};
                MMA_F32(s[n2*2],   qa[kc], kb0);
                MMA_F32(s[n2*2+1], qa[kc], kb1);
            }
        }

        // mask + scale
        #pragma unroll
        for (int n = 0; n < 8; n++) {
            int k0 = kbase + n*8 + 2*q;
            s[n][0] = (k0     <= qrow0) ? s[n][0]*SCALE_ATT : -1e30f;
            s[n][1] = (k0 + 1 <= qrow0) ? s[n][1]*SCALE_ATT : -1e30f;
            s[n][2] = (k0     <= qrow1) ? s[n][2]*SCALE_ATT : -1e30f;
            s[n][3] = (k0 + 1 <= qrow1) ? s[n][3]*SCALE_ATT : -1e30f;
        }

        // row max (quad reduce)
        float mx0 = -1e30f, mx1 = -1e30f;
        #pragma unroll
        for (int n = 0; n < 8; n++) {
            mx0 = fmaxf(mx0, fmaxf(s[n][0], s[n][1]));
            mx1 = fmaxf(mx1, fmaxf(s[n][2], s[n][3]));
        }
        mx0 = fmaxf(mx0, __shfl_xor_sync(0xffffffffu, mx0, 1));
        mx0 = fmaxf(mx0, __shfl_xor_sync(0xffffffffu, mx0, 2));
        mx1 = fmaxf(mx1, __shfl_xor_sync(0xffffffffu, mx1, 1));
        mx1 = fmaxf(mx1, __shfl_xor_sync(0xffffffffu, mx1, 2));

        float nm0 = fmaxf(m0, mx0), nm1 = fmaxf(m1, mx1);
        float cor0 = __expf(m0 - nm0), cor1 = __expf(m1 - nm1);
        m0 = nm0; m1 = nm1;
        l0 *= cor0; l1 *= cor1;
        #pragma unroll
        for (int n = 0; n < 8; n++) {
            oacc[n][0] *= cor0; oacc[n][1] *= cor0;
            oacc[n][2] *= cor1; oacc[n][3] *= cor1;
        }

        // p = exp(s - m), row sums
        float sum0 = 0.0f, sum1 = 0.0f;
        #pragma unroll
        for (int n = 0; n < 8; n++) {
            s[n][0] = __expf(s[n][0] - nm0); sum0 += s[n][0];
            s[n][1] = __expf(s[n][1] - nm0); sum0 += s[n][1];
            s[n][2] = __expf(s[n][2] - nm1); sum1 += s[n][2];
            s[n][3] = __expf(s[n][3] - nm1); sum1 += s[n][3];
        }
        sum0 += __shfl_xor_sync(0xffffffffu, sum0, 1);
        sum0 += __shfl_xor_sync(0xffffffffu, sum0, 2);
        sum1 += __shfl_xor_sync(0xffffffffu, sum1, 1);
        sum1 += __shfl_xor_sync(0xffffffffu, sum1, 2);
        l0 += sum0; l1 += sum1;

        // O += P @ V   (P A-frags from S C-frags; V B-frags via ldmatrix.trans)
        #pragma unroll
        for (int kc = 0; kc < 4; kc++) {
            uint32_t pa[4];
            pa[0] = pack2(s[2*kc][0],   s[2*kc][1]);
            pa[1] = pack2(s[2*kc][2],   s[2*kc][3]);
            pa[2] = pack2(s[2*kc+1][0], s[2*kc+1][1]);
            pa[3] = pack2(s[2*kc+1][2], s[2*kc+1][3]);
            #pragma unroll
            for (int n2 = 0; n2 < 4; n2++) {
                uint32_t r0, r1, r2, r3;
                LDSM4T(r0, r1, r2, r3, vfr + (uint32_t)kc*(16*APITCH) + n2*32);
                uint32_t vb0[2] = {r0, r1};
                uint32_t vb1[2] = {r2, r3};
                MMA_F32(oacc[n2*2],   pa, vb0);
                MMA_F32(oacc[n2*2+1], pa, vb1);
            }
        }
    }

    // epilogue: normalize, write fp16 y
    float inv0 = 1.0f / l0, inv1 = 1.0f / l1;
    size_t base0 = (size_t)(b*TT + qrow0) * DD + h*HDIM;
    size_t base1 = base0 + (size_t)8 * DD;
    #pragma unroll
    for (int n = 0; n < 8; n++) {
        int col = n*8 + 2*q;
        *(uint32_t*)(yh + base0 + col) = pack2(oacc[n][0]*inv0, oacc[n][1]*inv0);
        *(uint32_t*)(yh + base1 + col) = pack2(oacc[n][2]*inv1, oacc[n][3]*inv1);
    }
}

// ---------------------------------------------------------------------------
// NLL: single-pass online logsumexp
// ---------------------------------------------------------------------------
__global__ __launch_bounds__(256) void nll_kernel(
    const float* __restrict__ logits, const int* __restrict__ tgt,
    float* __restrict__ nll)
{
    __shared__ float rm[256];
    __shared__ float rs[256];
    int row = blockIdx.x;
    int tid = threadIdx.x;
    const float* lr = logits + (size_t)row * VV;

    float m = -3.4e38f, s = 0.0f;
    for (int i = tid; i < VV; i += 256) {
        float v = lr[i];
        if (v <= m) {
            s += __expf(v - m);
        } else {
            s = s * __expf(m - v) + 1.0f;
            m = v;
        }
    }
    rm[tid] = m; rs[tid] = s;
    __syncthreads();
    for (int o = 128; o > 0; o >>= 1) {
        if (tid < o) {
            float m2 = rm[tid + o], s2 = rs[tid + o];
            float M = fmaxf(rm[tid], m2);
            rs[tid] = rs[tid] * __expf(rm[tid] - M) + s2 * __expf(m2 - M);
            rm[tid] = M;
        }
        __syncthreads();
    }
    if (tid == 0) {
        float lse = rm[0] + logf(rs[0]);
        int tg = tgt[row];
        nll[row] = (tg != 0) ? (lse - lr[tg]) : 0.0f;
    }
}

__global__ __launch_bounds__(256) void loss_kernel(
    const float* __restrict__ nll, const int* __restrict__ tgt,
    float* __restrict__ out)
{
    __shared__ float s[256];
    __shared__ float c[256];
    int tid = threadIdx.x;
    float sv = 0.0f, cv = 0.0f;
    for (int i = tid; i < ROWS; i += 256) {
        sv += nll[i];
        cv += (tgt[i] != 0) ? 1.0f : 0.0f;
    }
    s[tid] = sv; c[tid] = cv; __syncthreads();
    for (int o = 128; o > 0; o >>= 1) {
        if (tid < o) { s[tid] += s[tid+o]; c[tid] += c[tid+o]; }
        __syncthreads();
    }
    if (tid == 0) out[0] = s[0] / fmaxf(c[0], 1.0f);
}

// ---------------------------------------------------------------------------
// Launcher
// ---------------------------------------------------------------------------
extern "C" void kernel_launch(void* const* d_in, const int* in_sizes, int n_in,
                              void* d_out, int out_size)
{
    const int*   idx   = (const int*)  d_in[0];
    const int*   tgt   = (const int*)  d_in[1];
    const float* tok   = (const float*)d_in[2];
    const float* pos   = (const float*)d_in[3];
    const float* ln1g  = (const float*)d_in[4];
    const float* ln1b  = (const float*)d_in[5];
    const float* wqkv  = (const float*)d_in[6];
    const float* bqkv  = (const float*)d_in[7];
    const float* wproj = (const float*)d_in[8];
    const float* bproj = (const float*)d_in[9];
    const float* ln2g  = (const float*)d_in[10];
    const float* ln2b  = (const float*)d_in[11];
    const float* w1    = (const float*)d_in[12];
    const float* b1    = (const float*)d_in[13];
    const float* w2    = (const float*)d_in[14];
    const float* b2    = (const float*)d_in[15];
    const float* lmw   = (const float*)d_in[16];

    float *px, *pqkv, *pnll;
    __half *ph, *py, *pm, *pxh;
    __half *pwqkvhi, *pwqkvlo, *pwprojhi, *pwprojlo;
    __half *pw1hi, *pw1lo, *pw2hi, *pw2lo, *plmwhi, *plmwlo;
    cudaGetSymbolAddress((void**)&px,     g_x);
    cudaGetSymbolAddress((void**)&pqkv,   g_qkv);
    cudaGetSymbolAddress((void**)&pnll,   g_nll);
    cudaGetSymbolAddress((void**)&ph,     g_h);
    cudaGetSymbolAddress((void**)&py,     g_y);
    cudaGetSymbolAddress((void**)&pm,     g_m);
    cudaGetSymbolAddress((void**)&pxh,    g_xh);
    cudaGetSymbolAddress((void**)&pwqkvhi,  g_wqkvThi);
    cudaGetSymbolAddress((void**)&pwqkvlo,  g_wqkvTlo);
    cudaGetSymbolAddress((void**)&pwprojhi, g_wprojThi);
    cudaGetSymbolAddress((void**)&pwprojlo, g_wprojTlo);
    cudaGetSymbolAddress((void**)&pw1hi,  g_w1Thi);
    cudaGetSymbolAddress((void**)&pw1lo,  g_w1Tlo);
    cudaGetSymbolAddress((void**)&pw2hi,  g_w2Thi);
    cudaGetSymbolAddress((void**)&pw2lo,  g_w2Tlo);
    cudaGetSymbolAddress((void**)&plmwhi, g_lmwThi);
    cudaGetSymbolAddress((void**)&plmwlo, g_lmwTlo);

    cudaFuncSetAttribute((const void*)hgemm_kernel<0>,
                         cudaFuncAttributeMaxDynamicSharedMemorySize, SMEM_DYN);
    cudaFuncSetAttribute((const void*)hgemm_kernel<1>,
                         cudaFuncAttributeMaxDynamicSharedMemorySize, SMEM_DYN);
    cudaFuncSetAttribute((const void*)hgemm_kernel<2>,
                         cudaFuncAttributeMaxDynamicSharedMemorySize, SMEM_DYN);

    float* out = (float*)d_out;

    // weight transposes + fp16 split (graph-captured each launch)
    tp_kernel<<<dim3(3*DD/32, DD/32, LL), 256>>>(
        wqkv, pwqkvhi, pwqkvlo, DD, 3*DD, 3*DD, (size_t)DD*3*DD, (size_t)3*DD*DD);
    tp_kernel<<<dim3(DD/32, DD/32, LL), 256>>>(
        wproj, pwprojhi, pwprojlo, DD, DD, DD, (size_t)DD*DD, (size_t)DD*DD);
    tp_kernel<<<dim3(4*DD/32, DD/32, LL), 256>>>(
        w1, pw1hi, pw1lo, DD, 4*DD, 4*DD, (size_t)DD*4*DD, (size_t)4*DD*DD);
    tp_kernel<<<dim3(DD/32, 4*DD/32, LL), 256>>>(
        w2, pw2hi, pw2lo, 4*DD, DD, DD, (size_t)4*DD*DD, (size_t)DD*4*DD);
    tp_kernel<<<dim3(VPAD/32, DD/32, 1), 256>>>(
        lmw, plmwhi, plmwlo, DD, VV, VPAD, 0, 0);

    embed_kernel<<<ROWS, 256>>>(idx, tok, pos, px);

    for (int l = 0; l < LL; l++) {
        ln_kernel<<<ROWS, 256>>>(px, ln1g + (size_t)l*DD, ln1b + (size_t)l*DD, ph);
        hgemm_kernel<0><<<dim3(ROWS/128, 3*DD/128), 512, SMEM_DYN>>>(
            ROWS, 3*DD, DD, ph,
            pwqkvhi + (size_t)l*3*DD*DD, pwqkvlo + (size_t)l*3*DD*DD,
            bqkv + (size_t)l*3*DD, nullptr, pqkv, nullptr);
        attn_kernel<<<dim3(BB*HH, TT/64), 128>>>(pqkv, py);
        hgemm_kernel<2><<<dim3(ROWS/128, DD/128), 512, SMEM_DYN>>>(
            ROWS, DD, DD, py,
            pwprojhi + (size_t)l*DD*DD, pwprojlo + (size_t)l*DD*DD,
            bproj + (size_t)l*DD, px, px, nullptr);
        ln_kernel<<<ROWS, 256>>>(px, ln2g + (size_t)l*DD, ln2b + (size_t)l*DD, ph);
        hgemm_kernel<1><<<dim3(ROWS/128, 4*DD/128), 512, SMEM_DYN>>>(
            ROWS, 4*DD, DD, ph,
            pw1hi + (size_t)l*4*DD*DD, pw1lo + (size_t)l*4*DD*DD,
            b1 + (size_t)l*4*DD, nullptr, nullptr, pm);
        hgemm_kernel<2><<<dim3(ROWS/128, DD/128), 512, SMEM_DYN>>>(
            ROWS, DD, 4*DD, pm,
            pw2hi + (size_t)l*DD*4*DD, pw2lo + (size_t)l*DD*4*DD,
            b2 + (size_t)l*DD, px, px, nullptr);
    }

    // quantize residual stream for LM head, then logits = x @ lm_w
    tohalf_kernel<<<ROWS, 256>>>(px, pxh);
    hgemm_kernel<0><<<dim3(ROWS/128, VPAD/128), 512, SMEM_DYN>>>(
        ROWS, VV, DD, pxh, plmwhi, plmwlo,
        nullptr, nullptr, out, nullptr);

    // loss
    nll_kernel<<<ROWS, 256>>>(out, tgt, pnll);
    size_t nlog = (size_t)ROWS * VV;
    if ((size_t)out_size > nlog) {
        loss_kernel<<<1, 256>>>(pnll, tgt, out + nlog);
    }
}

// round 12
// speedup vs baseline: 2.6933x; 1.5731x over previous
#include <cuda_runtime.h>
#include <cuda_fp16.h>
#include <math.h>
#include <stdint.h>

// Problem constants
#define BB 4
#define TT 1024
#define DD 1024
#define HH 16
#define HDIM 64
#define LL 8
#define VV 50257
#define VPAD 50432              // multiple of 256
#define ROWS (BB*TT)            // 4096
#define SCALE_ATT 0.07216878364870322f  // 1/sqrt(192)

// ---------------------------------------------------------------------------
// Scratch (static device globals; no runtime allocation)
// ---------------------------------------------------------------------------
__device__ float g_x   [ (size_t)ROWS * DD     ];   // residual stream (fp32)
__device__ float g_qkv [ (size_t)ROWS * 3 * DD ];   // qkv (fp32)
__device__ float g_nll [ ROWS ];
// plain fp16 activations
__device__ __half g_h  [ (size_t)ROWS * DD ];
__device__ __half g_y  [ (size_t)ROWS * DD ];
__device__ __half g_m  [ (size_t)ROWS * 4 * DD ];
__device__ __half g_xh [ (size_t)ROWS * DD ];
// fp16 transposed weights ([N,K] row-major)
__device__ __half g_wqkvT [ (size_t)LL * 3*DD * DD ];
__device__ __half g_wprojT[ (size_t)LL * DD * DD ];
__device__ __half g_w1T   [ (size_t)LL * 4*DD * DD ];
__device__ __half g_w2T   [ (size_t)LL * DD * 4*DD ];
__device__ __half g_lmwT  [ (size_t)VPAD * DD ];

// ---------------------------------------------------------------------------
// helpers
// ---------------------------------------------------------------------------
__device__ __forceinline__ uint32_t smem_u32(const void* p) {
    uint32_t a;
    asm("{ .reg .u64 t; cvta.to.shared.u64 t, %1; cvt.u32.u64 %0, t; }"
        : "=r"(a) : "l"(p));
    return a;
}
__device__ __forceinline__ uint32_t pack2(float x, float y) {
    __half hx = __float2half_rn(x);
    __half hy = __float2half_rn(y);
    return (uint32_t)__half_as_ushort(hx) | ((uint32_t)__half_as_ushort(hy) << 16);
}

#define MMA_F32(d, a, b) \
    asm volatile("mma.sync.aligned.m16n8k16.row.col.f32.f16.f16.f32 " \
        "{%0,%1,%2,%3}, {%4,%5,%6,%7}, {%8,%9}, {%0,%1,%2,%3};" \
        : "+f"((d)[0]), "+f"((d)[1]), "+f"((d)[2]), "+f"((d)[3]) \
        : "r"((a)[0]), "r"((a)[1]), "r"((a)[2]), "r"((a)[3]), \
          "r"((b)[0]), "r"((b)[1]))

#define LDSM4(r0, r1, r2, r3, addr) \
    asm volatile("ldmatrix.sync.aligned.m8n8.x4.shared.b16 {%0,%1,%2,%3}, [%4];" \
        : "=r"(r0), "=r"(r1), "=r"(r2), "=r"(r3) : "r"(addr))

#define LDSM4T(r0, r1, r2, r3, addr) \
    asm volatile("ldmatrix.sync.aligned.m8n8.x4.trans.shared.b16 {%0,%1,%2,%3}, [%4];" \
        : "=r"(r0), "=r"(r1), "=r"(r2), "=r"(r3) : "r"(addr))

__device__ __forceinline__ void cp16(uint32_t d, const void* g) {
    asm volatile("cp.async.cg.shared.global [%0], [%1], 16;" :: "r"(d), "l"(g));
}
#define CP_COMMIT() asm volatile("cp.async.commit_group;" ::: "memory")
#define CP_WAIT0()  asm volatile("cp.async.wait_group 0;" ::: "memory")
#define CP_WAIT1()  asm volatile("cp.async.wait_group 1;" ::: "memory")

// ---------------------------------------------------------------------------
// fp16 tensor GEMM: C[M,N] = A[M,K] @ Bt[N,K]^T (+bias)(+relu/+res)
// CTA tile 128x256, K-chunk 32, 2-stage cp.async, 512 threads.
// Warp grid 4m x 4n, warp tile 32x64. One fp32-acc MMA per k-step.
// EPI: 0=bias->f32, 1=bias+relu->fp16, 2=bias+residual->f32.
// smem per buffer: A(128x80B) | B(256x80B). Epilogue staged per 128-col half.
// ---------------------------------------------------------------------------
#define ATILE 10240            // 128 * 80
#define BTILE 20480            // 256 * 80
#define BUFB  (ATILE + BTILE)  // 30720
#define SMEM_DYN 67840         // max(2*BUFB=61440, Cs=128*132*4=67584)

template<int EPI>
__global__ __launch_bounds__(512) void hgemm_kernel(
    int M, int N, int K,
    const __half* __restrict__ A, const __half* __restrict__ Bt,
    const float* __restrict__ bias, const float* __restrict__ res,
    float* __restrict__ C, __half* __restrict__ Ch)
{
    extern __shared__ __align__(128) char smem[];
    const uint32_t sb = smem_u32(smem);
    const int tid  = threadIdx.x;
    const int wid  = tid >> 5;
    const int lane = tid & 31;
    const int mbase = blockIdx.x * 128;
    const int nbase = blockIdx.y * 256;
    const int warp_m = wid & 3;          // 0..3 (32 rows)
    const int warp_n = wid >> 2;         // 0..3 (64 cols)
    const int g = lane >> 2;
    const int q = lane & 3;

    const uint32_t aoff = (uint32_t)(warp_m*32 + (lane & 15)) * 80
                        + ((lane >> 4) & 1) * 16;
    const uint32_t boff = ATILE
                        + (uint32_t)(warp_n*64 + (lane & 7) + ((lane >> 4) & 1)*8) * 80
                        + ((lane >> 3) & 1) * 16;

    float acc[2][8][4];
    #pragma unroll
    for (int m = 0; m < 2; m++)
        #pragma unroll
        for (int n = 0; n < 8; n++)
            #pragma unroll
            for (int r = 0; r < 4; r++) acc[m][n][r] = 0.0f;

    const int nch = K >> 5;

    // loader: A 512 transfers + B 1024 transfers of 16B, 3 per thread
    auto issue = [&](uint32_t dstbase, int k0) {
        const int arow = tid >> 2, aseg = tid & 3;
        cp16(dstbase + (uint32_t)arow*80 + aseg*16,
             A + (size_t)(mbase+arow)*K + k0 + aseg*8);
        #pragma unroll
        for (int i = 0; i < 2; i++) {
            int v = i*512 + tid;
            int row = v >> 2, seg = v & 3;
            cp16(dstbase + ATILE + (uint32_t)row*80 + seg*16,
                 Bt + (size_t)(nbase+row)*K + k0 + seg*8);
        }
    };

    issue(sb, 0);
    CP_COMMIT();

    for (int it = 0; it < nch; it++) {
        if (it + 1 < nch) {
            issue(sb + ((it+1) & 1) * BUFB, (it+1) << 5);
            CP_COMMIT();
            CP_WAIT1();
        } else {
            CP_WAIT0();
        }
        __syncthreads();

        const uint32_t bufu = sb + (it & 1) * BUFB;

        #pragma unroll
        for (int ks = 0; ks < 32; ks += 16) {
            uint32_t ar[2][4], bh[8][2];
            #pragma unroll
            for (int m = 0; m < 2; m++) {
                uint32_t ad = bufu + aoff + m*(16*80) + ks*2;
                LDSM4(ar[m][0], ar[m][1], ar[m][2], ar[m][3], ad);
            }
            #pragma unroll
            for (int n2 = 0; n2 < 4; n2++) {
                uint32_t bd = bufu + boff + (uint32_t)n2*(16*80) + ks*2;
                uint32_t r0, r1, r2, r3;
                LDSM4(r0, r1, r2, r3, bd);
                bh[n2*2][0] = r0; bh[n2*2][1] = r1;
                bh[n2*2+1][0] = r2; bh[n2*2+1][1] = r3;
            }
            #pragma unroll
            for (int m = 0; m < 2; m++)
                #pragma unroll
                for (int n = 0; n < 8; n++)
                    MMA_F32(acc[m][n], ar[m], bh[n]);
        }
        __syncthreads();
    }

    // epilogue: two 128-col halves staged through smem
    float* Cs = (float*)smem;   // [128][132]
    #pragma unroll
    for (int half = 0; half < 2; half++) {
        if ((warp_n >> 1) == half) {
            int cb = (warp_n & 1) * 64;
            #pragma unroll
            for (int m = 0; m < 2; m++) {
                int r0 = warp_m*32 + m*16 + g;
                #pragma unroll
                for (int n = 0; n < 8; n++) {
                    int col = cb + n*8 + 2*q;
                    Cs[r0*132 + col]       = acc[m][n][0];
                    Cs[r0*132 + col + 1]   = acc[m][n][1];
                    Cs[(r0+8)*132 + col]   = acc[m][n][2];
                    Cs[(r0+8)*132 + col+1] = acc[m][n][3];
                }
            }
        }
        __syncthreads();

        const int nb = nbase + half*128;
        if (EPI == 1) {
            #pragma unroll
            for (int i = 0; i < 8; i++) {
                int u = tid + i*512;
                int row = u >> 5, c4 = (u & 31) * 4;
                int col = nb + c4;
                float v0 = Cs[row*132 + c4 + 0] + bias[col];
                float v1 = Cs[row*132 + c4 + 1] + bias[col+1];
                float v2 = Cs[row*132 + c4 + 2] + bias[col+2];
                float v3 = Cs[row*132 + c4 + 3] + bias[col+3];
                v0 = fmaxf(v0, 0.f); v1 = fmaxf(v1, 0.f);
                v2 = fmaxf(v2, 0.f); v3 = fmaxf(v3, 0.f);
                uint2 hv;
                hv.x = pack2(v0, v1);
                hv.y = pack2(v2, v3);
                *(uint2*)(Ch + (size_t)(mbase+row)*N + col) = hv;
            }
        } else if ((N & 3) == 0) {
            #pragma unroll
            for (int i = 0; i < 8; i++) {
                int u = tid + i*512;
                int row = u >> 5, c4 = (u & 31) * 4;
                int col = nb + c4;
                float v0 = Cs[row*132 + c4 + 0];
                float v1 = Cs[row*132 + c4 + 1];
                float v2 = Cs[row*132 + c4 + 2];
                float v3 = Cs[row*132 + c4 + 3];
                if (bias) { v0 += bias[col]; v1 += bias[col+1]; v2 += bias[col+2]; v3 += bias[col+3]; }
                if (EPI == 2) {
                    const float4 rv = *(const float4*)(res + (size_t)(mbase+row)*N + col);
                    v0 += rv.x; v1 += rv.y; v2 += rv.z; v3 += rv.w;
                }
                *(float4*)(C + (size_t)(mbase+row)*N + col) = make_float4(v0, v1, v2, v3);
            }
        } else {
            #pragma unroll
            for (int i = 0; i < 8; i++) {
                int u = tid + i*512;
                int row = u >> 5, c4 = (u & 31) * 4;
                float* crow = C + (size_t)(mbase+row)*N;
                #pragma unroll
                for (int j = 0; j < 4; j++) {
                    int col = nb + c4 + j;
                    if (col < N) {
                        float v = Cs[row*132 + c4 + j];
                        if (bias) v += bias[col];
                        if (EPI == 2) v += res[(size_t)(mbase+row)*N + col];
                        crow[col] = v;
                    }
                }
            }
        }
        __syncthreads();
    }
}

// ---------------------------------------------------------------------------
// Tiled transpose to fp16: in [K,N] -> out [Npad,K], zero-pad rows >= N
// ---------------------------------------------------------------------------
__global__ __launch_bounds__(256) void tp_kernel(
    const float* __restrict__ in, __half* __restrict__ out,
    int K, int N, int Npad, size_t inStride, size_t outStride)
{
    __shared__ float t[32][33];
    const float* ip = in + blockIdx.z * inStride;
    __half* op = out + blockIdx.z * outStride;
    int n0 = blockIdx.x * 32, k0 = blockIdx.y * 32;
    int tx = threadIdx.x & 31, ty = threadIdx.x >> 5;
    #pragma unroll
    for (int j = ty; j < 32; j += 8) {
        int k = k0 + j, n = n0 + tx;
        t[j][tx] = (k < K && n < N) ? ip[(size_t)k * N + n] : 0.0f;
    }
    __syncthreads();
    #pragma unroll
    for (int j = ty; j < 32; j += 8) {
        int n = n0 + j, k = k0 + tx;
        if (n < Npad && k < K)
            op[(size_t)n * K + k] = __float2half_rn(t[tx][j]);
    }
}

// ---------------------------------------------------------------------------
// Elementwise fp16 quantize (LM-head input)
// ---------------------------------------------------------------------------
__global__ __launch_bounds__(256) void tohalf_kernel(
    const float* __restrict__ x, __half* __restrict__ xh)
{
    size_t i = ((size_t)blockIdx.x * 256 + threadIdx.x) * 4;
    float4 v = *(const float4*)(x + i);
    uint2 hv;
    hv.x = pack2(v.x, v.y);
    hv.y = pack2(v.z, v.w);
    *(uint2*)(xh + i) = hv;
}

// ---------------------------------------------------------------------------
// Embedding
// ---------------------------------------------------------------------------
__global__ __launch_bounds__(256) void embed_kernel(
    const int* __restrict__ idx, const float* __restrict__ tok,
    const float* __restrict__ pos, float* __restrict__ x)
{
    int row = blockIdx.x;
    int t   = row & (TT - 1);
    int id  = idx[row];
    const float4* tp = (const float4*)(tok + (size_t)id * DD);
    const float4* pp = (const float4*)(pos + (size_t)t  * DD);
    float4*       xp = (float4*)(x + (size_t)row * DD);
    int i = threadIdx.x;
    float4 a = tp[i], b = pp[i];
    a.x += b.x; a.y += b.y; a.z += b.z; a.w += b.w;
    xp[i] = a;
}

// ---------------------------------------------------------------------------
// LayerNorm -> plain fp16 output
// ---------------------------------------------------------------------------
__global__ __launch_bounds__(256) void ln_kernel(
    const float* __restrict__ x, const float* __restrict__ g,
    const float* __restrict__ b, __half* __restrict__ oh)
{
    __shared__ float s1[256];
    __shared__ float s2[256];
    int row = blockIdx.x;
    int tid = threadIdx.x;
    float4 v = ((const float4*)(x + (size_t)row * DD))[tid];
    float s  = v.x + v.y + v.z + v.w;
    float ss = v.x*v.x + v.y*v.y + v.z*v.z + v.w*v.w;
    s1[tid] = s; s2[tid] = ss;
    __syncthreads();
    for (int o = 128; o > 0; o >>= 1) {
        if (tid < o) { s1[tid] += s1[tid+o]; s2[tid] += s2[tid+o]; }
        __syncthreads();
    }
    float mu   = s1[0] * (1.0f / DD);
    float var  = s2[0] * (1.0f / DD) - mu * mu;
    float rstd = rsqrtf(var + 1e-5f);
    float4 gv = ((const float4*)g)[tid];
    float4 bv = ((const float4*)b)[tid];
    float o0 = (v.x - mu) * rstd * gv.x + bv.x;
    float o1 = (v.y - mu) * rstd * gv.y + bv.y;
    float o2 = (v.z - mu) * rstd * gv.z + bv.z;
    float o3 = (v.w - mu) * rstd * gv.w + bv.w;
    uint2 hv;
    hv.x = pack2(o0, o1);
    hv.y = pack2(o2, o3);
    *(uint2*)(oh + (size_t)row * DD + tid * 4) = hv;
}

// ---------------------------------------------------------------------------
// Tensor-core flash attention (unchanged from R11).
// Block = 128 threads (4 warps): one (b,h), 64-query tile. Grid (B*H, T/64).
// ---------------------------------------------------------------------------
#define APITCH 144

__global__ __launch_bounds__(128) void attn_kernel(
    const float* __restrict__ qkv, __half* __restrict__ yh)
{
    __shared__ __align__(16) char sm[3 * 64 * APITCH];
    char* Qs = sm;
    char* Ks = sm + 64*APITCH;
    char* Vs = sm + 2*64*APITCH;

    const int tid  = threadIdx.x;
    const int wid  = tid >> 5;
    const int lane = tid & 31;
    const int g = lane >> 2;
    const int q = lane & 3;
    const int bh = blockIdx.x;
    const int b  = bh >> 4;
    const int h  = bh & (HH - 1);
    const int qbase = blockIdx.y * 64;

    {
        int row = tid >> 1;
        int c0  = (tid & 1) * 32;
        const float* src = qkv + (size_t)(b*TT + qbase + row)*(3*DD) + h*HDIM + c0;
        char* dp = Qs + row*APITCH + c0*2;
        #pragma unroll
        for (int j = 0; j < 4; j++) {
            float4 v0 = *(const float4*)(src + j*8);
            float4 v1 = *(const float4*)(src + j*8 + 4);
            uint4 o;
            o.x = pack2(v0.x, v0.y); o.y = pack2(v0.z, v0.w);
            o.z = pack2(v1.x, v1.y); o.w = pack2(v1.z, v1.w);
            *(uint4*)(dp + j*16) = o;
        }
    }
    __syncthreads();

    uint32_t qa[4][4];
    {
        uint32_t qaddr = smem_u32(Qs) + (uint32_t)(wid*16 + (lane & 15))*APITCH
                       + ((lane >> 4) & 1) * 16;
        #pragma unroll
        for (int c = 0; c < 4; c++)
            LDSM4(qa[c][0], qa[c][1], qa[c][2], qa[c][3], qaddr + c*32);
    }

    const int qrow0 = qbase + wid*16 + g;
    const int qrow1 = qrow0 + 8;

    float m0 = -1e30f, m1 = -1e30f, l0 = 0.0f, l1 = 0.0f;
    float oacc[8][4];
    #pragma unroll
    for (int n = 0; n < 8; n++)
        #pragma unroll
        for (int r = 0; r < 4; r++) oacc[n][r] = 0.0f;

    const uint32_t kfr = smem_u32(Ks) + (uint32_t)((lane & 7) + ((lane >> 4) & 1)*8)*APITCH
                       + ((lane >> 3) & 1) * 16;
    const uint32_t vfr = smem_u32(Vs) + (uint32_t)((lane & 7) + ((lane >> 3) & 1)*8)*APITCH
                       + ((lane >> 4) & 1) * 16;

    const int ntiles = blockIdx.y + 1;
    for (int kt = 0; kt < ntiles; kt++) {
        const int kbase = kt * 64;
        __syncthreads();
        {
            int row = tid >> 1;
            int c0  = (tid & 1) * 32;
            const float* sk = qkv + (size_t)(b*TT + kbase + row)*(3*DD) + DD   + h*HDIM + c0;
            const float* sv = qkv + (size_t)(b*TT + kbase + row)*(3*DD) + 2*DD + h*HDIM + c0;
            char* dk = Ks + row*APITCH + c0*2;
            char* dv = Vs + row*APITCH + c0*2;
            #pragma unroll
            for (int j = 0; j < 4; j++) {
                float4 v0 = *(const float4*)(sk + j*8);
                float4 v1 = *(const float4*)(sk + j*8 + 4);
                uint4 o;
                o.x = pack2(v0.x, v0.y); o.y = pack2(v0.z, v0.w);
                o.z = pack2(v1.x, v1.y); o.w = pack2(v1.z, v1.w);
                *(uint4*)(dk + j*16) = o;
                v0 = *(const float4*)(sv + j*8);
                v1 = *(const float4*)(sv + j*8 + 4);
                o.x = pack2(v0.x, v0.y); o.y = pack2(v0.z, v0.w);
                o.z = pack2(v1.x, v1.y); o.w = pack2(v1.z, v1.w);
                *(uint4*)(dv + j*16) = o;
            }
        }
        __syncthreads();

        float s[8][4];
        #pragma unroll
        for (int n = 0; n < 8; n++)
            #pragma unroll
            for (int r = 0; r < 4; r++) s[n][r] = 0.0f;
        #pragma unroll
        for (int kc = 0; kc < 4; kc++) {
            #pragma unroll
            for (int n2 = 0; n2 < 4; n2++) {
                uint32_t r0, r1, r2, r3;
                LDSM4(r0, r1, r2, r3, kfr + (uint32_t)n2*(16*APITCH) + kc*32);
                uint32_t kb0[2] = {r0, r1};
                uint32_t kb1[2] = {r2, r3};
                MMA_F32(s[n2*2],   qa[kc], kb0);
                MMA_F32(s[n2*2+1], qa[kc], kb1);
            }
        }

        #pragma unroll
        for (int n = 0; n < 8; n++) {
            int k0 = kbase + n*8 + 2*q;
            s[n][0] = (k0     <= qrow0) ? s[n][0]*SCALE_ATT : -1e30f;
            s[n][1] = (k0 + 1 <= qrow0) ? s[n][1]*SCALE_ATT : -1e30f;
            s[n][2] = (k0     <= qrow1) ? s[n][2]*SCALE_ATT : -1e30f;
            s[n][3] = (k0 + 1 <= qrow1) ? s[n][3]*SCALE_ATT : -1e30f;
        }

        float mx0 = -1e30f, mx1 = -1e30f;
        #pragma unroll
        for (int n = 0; n < 8; n++) {
            mx0 = fmaxf(mx0, fmaxf(s[n][0], s[n][1]));
            mx1 = fmaxf(mx1, fmaxf(s[n][2], s[n][3]));
        }
        mx0 = fmaxf(mx0, __shfl_xor_sync(0xffffffffu, mx0, 1));
        mx0 = fmaxf(mx0, __shfl_xor_sync(0xffffffffu, mx0, 2));
        mx1 = fmaxf(mx1, __shfl_xor_sync(0xffffffffu, mx1, 1));
        mx1 = fmaxf(mx1, __shfl_xor_sync(0xffffffffu, mx1, 2));

        float nm0 = fmaxf(m0, mx0), nm1 = fmaxf(m1, mx1);
        float cor0 = __expf(m0 - nm0), cor1 = __expf(m1 - nm1);
        m0 = nm0; m1 = nm1;
        l0 *= cor0; l1 *= cor1;
        #pragma unroll
        for (int n = 0; n < 8; n++) {
            oacc[n][0] *= cor0; oacc[n][1] *= cor0;
            oacc[n][2] *= cor1; oacc[n][3] *= cor1;
        }

        float sum0 = 0.0f, sum1 = 0.0f;
        #pragma unroll
        for (int n = 0; n < 8; n++) {
            s[n][0] = __expf(s[n][0] - nm0); sum0 += s[n][0];
            s[n][1] = __expf(s[n][1] - nm0); sum0 += s[n][1];
            s[n][2] = __expf(s[n][2] - nm1); sum1 += s[n][2];
            s[n][3] = __expf(s[n][3] - nm1); sum1 += s[n][3];
        }
        sum0 += __shfl_xor_sync(0xffffffffu, sum0, 1);
        sum0 += __shfl_xor_sync(0xffffffffu, sum0, 2);
        sum1 += __shfl_xor_sync(0xffffffffu, sum1, 1);
        sum1 += __shfl_xor_sync(0xffffffffu, sum1, 2);
        l0 += sum0; l1 += sum1;

        #pragma unroll
        for (int kc = 0; kc < 4; kc++) {
            uint32_t pa[4];
            pa[0] = pack2(s[2*kc][0],   s[2*kc][1]);
            pa[1] = pack2(s[2*kc][2],   s[2*kc][3]);
            pa[2] = pack2(s[2*kc+1][0], s[2*kc+1][1]);
            pa[3] = pack2(s[2*kc+1][2], s[2*kc+1][3]);
            #pragma unroll
            for (int n2 = 0; n2 < 4; n2++) {
                uint32_t r0, r1, r2, r3;
                LDSM4T(r0, r1, r2, r3, vfr + (uint32_t)kc*(16*APITCH) + n2*32);
                uint32_t vb0[2] = {r0, r1};
                uint32_t vb1[2] = {r2, r3};
                MMA_F32(oacc[n2*2],   pa, vb0);
                MMA_F32(oacc[n2*2+1], pa, vb1);
            }
        }
    }

    float inv0 = 1.0f / l0, inv1 = 1.0f / l1;
    size_t base0 = (size_t)(b*TT + qrow0) * DD + h*HDIM;
    size_t base1 = base0 + (size_t)8 * DD;
    #pragma unroll
    for (int n = 0; n < 8; n++) {
        int col = n*8 + 2*q;
        *(uint32_t*)(yh + base0 + col) = pack2(oacc[n][0]*inv0, oacc[n][1]*inv0);
        *(uint32_t*)(yh + base1 + col) = pack2(oacc[n][2]*inv1, oacc[n][3]*inv1);
    }
}

// ---------------------------------------------------------------------------
// NLL: single-pass online logsumexp
// ---------------------------------------------------------------------------
__global__ __launch_bounds__(256) void nll_kernel(
    const float* __restrict__ logits, const int* __restrict__ tgt,
    float* __restrict__ nll)
{
    __shared__ float rm[256];
    __shared__ float rs[256];
    int row = blockIdx.x;
    int tid = threadIdx.x;
    const float* lr = logits + (size_t)row * VV;

    float m = -3.4e38f, s = 0.0f;
    for (int i = tid; i < VV; i += 256) {
        float v = lr[i];
        if (v <= m) {
            s += __expf(v - m);
        } else {
            s = s * __expf(m - v) + 1.0f;
            m = v;
        }
    }
    rm[tid] = m; rs[tid] = s;
    __syncthreads();
    for (int o = 128; o > 0; o >>= 1) {
        if (tid < o) {
            float m2 = rm[tid + o], s2 = rs[tid + o];
            float M = fmaxf(rm[tid], m2);
            rs[tid] = rs[tid] * __expf(rm[tid] - M) + s2 * __expf(m2 - M);
            rm[tid] = M;
        }
        __syncthreads();
    }
    if (tid == 0) {
        float lse = rm[0] + logf(rs[0]);
        int tg = tgt[row];
        nll[row] = (tg != 0) ? (lse - lr[tg]) : 0.0f;
    }
}

__global__ __launch_bounds__(256) void loss_kernel(
    const float* __restrict__ nll, const int* __restrict__ tgt,
    float* __restrict__ out)
{
    __shared__ float s[256];
    __shared__ float c[256];
    int tid = threadIdx.x;
    float sv = 0.0f, cv = 0.0f;
    for (int i = tid; i < ROWS; i += 256) {
        sv += nll[i];
        cv += (tgt[i] != 0) ? 1.0f : 0.0f;
    }
    s[tid] = sv; c[tid] = cv; __syncthreads();
    for (int o = 128; o > 0; o >>= 1) {
        if (tid < o) { s[tid] += s[tid+o]; c[tid] += c[tid+o]; }
        __syncthreads();
    }
    if (tid == 0) out[0] = s[0] / fmaxf(c[0], 1.0f);
}

// ---------------------------------------------------------------------------
// Launcher
// ---------------------------------------------------------------------------
extern "C" void kernel_launch(void* const* d_in, const int* in_sizes, int n_in,
                              void* d_out, int out_size)
{
    const int*   idx   = (const int*)  d_in[0];
    const int*   tgt   = (const int*)  d_in[1];
    const float* tok   = (const float*)d_in[2];
    const float* pos   = (const float*)d_in[3];
    const float* ln1g  = (const float*)d_in[4];
    const float* ln1b  = (const float*)d_in[5];
    const float* wqkv  = (const float*)d_in[6];
    const float* bqkv  = (const float*)d_in[7];
    const float* wproj = (const float*)d_in[8];
    const float* bproj = (const float*)d_in[9];
    const float* ln2g  = (const float*)d_in[10];
    const float* ln2b  = (const float*)d_in[11];
    const float* w1    = (const float*)d_in[12];
    const float* b1    = (const float*)d_in[13];
    const float* w2    = (const float*)d_in[14];
    const float* b2    = (const float*)d_in[15];
    const float* lmw   = (const float*)d_in[16];

    float *px, *pqkv, *pnll;
    __half *ph, *py, *pm, *pxh;
    __half *pwqkv, *pwproj, *pw1, *pw2, *plmw;
    cudaGetSymbolAddress((void**)&px,    g_x);
    cudaGetSymbolAddress((void**)&pqkv,  g_qkv);
    cudaGetSymbolAddress((void**)&pnll,  g_nll);
    cudaGetSymbolAddress((void**)&ph,    g_h);
    cudaGetSymbolAddress((void**)&py,    g_y);
    cudaGetSymbolAddress((void**)&pm,    g_m);
    cudaGetSymbolAddress((void**)&pxh,   g_xh);
    cudaGetSymbolAddress((void**)&pwqkv, g_wqkvT);
    cudaGetSymbolAddress((void**)&pwproj,g_wprojT);
    cudaGetSymbolAddress((void**)&pw1,   g_w1T);
    cudaGetSymbolAddress((void**)&pw2,   g_w2T);
    cudaGetSymbolAddress((void**)&plmw,  g_lmwT);

    cudaFuncSetAttribute((const void*)hgemm_kernel<0>,
                         cudaFuncAttributeMaxDynamicSharedMemorySize, SMEM_DYN);
    cudaFuncSetAttribute((const void*)hgemm_kernel<1>,
                         cudaFuncAttributeMaxDynamicSharedMemorySize, SMEM_DYN);
    cudaFuncSetAttribute((const void*)hgemm_kernel<2>,
                         cudaFuncAttributeMaxDynamicSharedMemorySize, SMEM_DYN);

    float* out = (float*)d_out;

    // weight transposes to fp16 (graph-captured each launch)
    tp_kernel<<<dim3(3*DD/32, DD/32, LL), 256>>>(
        wqkv, pwqkv, DD, 3*DD, 3*DD, (size_t)DD*3*DD, (size_t)3*DD*DD);
    tp_kernel<<<dim3(DD/32, DD/32, LL), 256>>>(
        wproj, pwproj, DD, DD, DD, (size_t)DD*DD, (size_t)DD*DD);
    tp_kernel<<<dim3(4*DD/32, DD/32, LL), 256>>>(
        w1, pw1, DD, 4*DD, 4*DD, (size_t)DD*4*DD, (size_t)4*DD*DD);
    tp_kernel<<<dim3(DD/32, 4*DD/32, LL), 256>>>(
        w2, pw2, 4*DD, DD, DD, (size_t)4*DD*DD, (size_t)DD*4*DD);
    tp_kernel<<<dim3(VPAD/32, DD/32, 1), 256>>>(
        lmw, plmw, DD, VV, VPAD, 0, 0);

    embed_kernel<<<ROWS, 256>>>(idx, tok, pos, px);

    for (int l = 0; l < LL; l++) {
        ln_kernel<<<ROWS, 256>>>(px, ln1g + (size_t)l*DD, ln1b + (size_t)l*DD, ph);
        hgemm_kernel<0><<<dim3(ROWS/128, 3*DD/256), 512, SMEM_DYN>>>(
            ROWS, 3*DD, DD, ph, pwqkv + (size_t)l*3*DD*DD,
            bqkv + (size_t)l*3*DD, nullptr, pqkv, nullptr);
        attn_kernel<<<dim3(BB*HH, TT/64), 128>>>(pqkv, py);
        hgemm_kernel<2><<<dim3(ROWS/128, DD/256), 512, SMEM_DYN>>>(
            ROWS, DD, DD, py, pwproj + (size_t)l*DD*DD,
            bproj + (size_t)l*DD, px, px, nullptr);
        ln_kernel<<<ROWS, 256>>>(px, ln2g + (size_t)l*DD, ln2b + (size_t)l*DD, ph);
        hgemm_kernel<1><<<dim3(ROWS/128, 4*DD/256), 512, SMEM_DYN>>>(
            ROWS, 4*DD, DD, ph, pw1 + (size_t)l*4*DD*DD,
            b1 + (size_t)l*4*DD, nullptr, nullptr, pm);
        hgemm_kernel<2><<<dim3(ROWS/128, DD/256), 512, SMEM_DYN>>>(
            ROWS, DD, 4*DD, pm, pw2 + (size_t)l*DD*4*DD,
            b2 + (size_t)l*DD, px, px, nullptr);
    }

    // quantize residual stream for LM head, then logits = x @ lm_w
    tohalf_kernel<<<ROWS, 256>>>(px, pxh);
    hgemm_kernel<0><<<dim3(ROWS/128, VPAD/256), 512, SMEM_DYN>>>(
        ROWS, VV, DD, pxh, plmw, nullptr, nullptr, out, nullptr);

    // loss
    nll_kernel<<<ROWS, 256>>>(out, tgt, pnll);
    size_t nlog = (size_t)ROWS * VV;
    if ((size_t)out_size > nlog) {
        loss_kernel<<<1, 256>>>(pnll, tgt, out + nlog);
    }
}

// round 13
// speedup vs baseline: 3.0202x; 1.1214x over previous
#include <cuda_runtime.h>
#include <cuda_fp16.h>
#include <math.h>
#include <stdint.h>

// Problem constants
#define BB 4
#define TT 1024
#define DD 1024
#define HH 16
#define HDIM 64
#define LL 8
#define VV 50257
#define VPAD 50432              // multiple of 256
#define NT2LM ((VPAD/256)*2)    // 394 logsumexp partials per row
#define ROWS (BB*TT)            // 4096
#define SCALE_ATT 0.07216878364870322f  // 1/sqrt(192)

// ---------------------------------------------------------------------------
// Scratch (static device globals; no runtime allocation)
// ---------------------------------------------------------------------------
__device__ float g_x   [ (size_t)ROWS * DD     ];
__device__ float g_qkv [ (size_t)ROWS * 3 * DD ];
__device__ float g_nll [ ROWS ];
__device__ float2 g_part[ (size_t)ROWS * NT2LM ];   // LM logsumexp partials
// plain fp16 activations
__device__ __half g_h  [ (size_t)ROWS * DD ];
__device__ __half g_y  [ (size_t)ROWS * DD ];
__device__ __half g_m  [ (size_t)ROWS * 4 * DD ];
__device__ __half g_xh [ (size_t)ROWS * DD ];
// fp16 transposed weights ([N,K] row-major)
__device__ __half g_wqkvT [ (size_t)LL * 3*DD * DD ];
__device__ __half g_wprojT[ (size_t)LL * DD * DD ];
__device__ __half g_w1T   [ (size_t)LL * 4*DD * DD ];
__device__ __half g_w2T   [ (size_t)LL * DD * 4*DD ];
__device__ __half g_lmwT  [ (size_t)VPAD * DD ];

// ---------------------------------------------------------------------------
// helpers
// ---------------------------------------------------------------------------
__device__ __forceinline__ uint32_t smem_u32(const void* p) {
    uint32_t a;
    asm("{ .reg .u64 t; cvta.to.shared.u64 t, %1; cvt.u32.u64 %0, t; }"
        : "=r"(a) : "l"(p));
    return a;
}
__device__ __forceinline__ uint32_t pack2(float x, float y) {
    __half hx = __float2half_rn(x);
    __half hy = __float2half_rn(y);
    return (uint32_t)__half_as_ushort(hx) | ((uint32_t)__half_as_ushort(hy) << 16);
}

#define MMA_F32(d, a, b) \
    asm volatile("mma.sync.aligned.m16n8k16.row.col.f32.f16.f16.f32 " \
        "{%0,%1,%2,%3}, {%4,%5,%6,%7}, {%8,%9}, {%0,%1,%2,%3};" \
        : "+f"((d)[0]), "+f"((d)[1]), "+f"((d)[2]), "+f"((d)[3]) \
        : "r"((a)[0]), "r"((a)[1]), "r"((a)[2]), "r"((a)[3]), \
          "r"((b)[0]), "r"((b)[1]))

#define LDSM4(r0, r1, r2, r3, addr) \
    asm volatile("ldmatrix.sync.aligned.m8n8.x4.shared.b16 {%0,%1,%2,%3}, [%4];" \
        : "=r"(r0), "=r"(r1), "=r"(r2), "=r"(r3) : "r"(addr))

#define LDSM4T(r0, r1, r2, r3, addr) \
    asm volatile("ldmatrix.sync.aligned.m8n8.x4.trans.shared.b16 {%0,%1,%2,%3}, [%4];" \
        : "=r"(r0), "=r"(r1), "=r"(r2), "=r"(r3) : "r"(addr))

__device__ __forceinline__ void cp16(uint32_t d, const void* g) {
    asm volatile("cp.async.cg.shared.global [%0], [%1], 16;" :: "r"(d), "l"(g));
}
#define CP_COMMIT() asm volatile("cp.async.commit_group;" ::: "memory")
#define CP_WAIT0()  asm volatile("cp.async.wait_group 0;" ::: "memory")
#define CP_WAIT1()  asm volatile("cp.async.wait_group 1;" ::: "memory")

// ---------------------------------------------------------------------------
// fp16 tensor GEMM: C[M,N] = A[M,K] @ Bt[N,K]^T (+bias)(+relu/+res)
// CTA tile 128x256, K-chunk 64, 2-stage cp.async, 512 threads.
// Warp grid 4m x 4n, warp tile 32x64. 144B row pitch (conflict-free).
// EPI: 0=bias->f32 (+opt logsumexp partials), 1=bias+relu->fp16, 2=+res->f32.
// ---------------------------------------------------------------------------
#define PITCH 144
#define ATILE (128*PITCH)        // 18432
#define BTILE (256*PITCH)        // 36864
#define BUFB  (ATILE + BTILE)    // 55296
#define SMEM_DYN (2*BUFB)        // 110592; epilogue Cs (128*132*4=67584) fits

template<int EPI>
__global__ __launch_bounds__(512) void hgemm_kernel(
    int M, int N, int K,
    const __half* __restrict__ A, const __half* __restrict__ Bt,
    const float* __restrict__ bias, const float* __restrict__ res,
    float* __restrict__ C, __half* __restrict__ Ch,
    float2* __restrict__ part)
{
    extern __shared__ __align__(128) char smem[];
    const uint32_t sb = smem_u32(smem);
    const int tid  = threadIdx.x;
    const int wid  = tid >> 5;
    const int lane = tid & 31;
    const int mbase = blockIdx.x * 128;
    const int nbase = blockIdx.y * 256;
    const int warp_m = wid & 3;
    const int warp_n = wid >> 2;
    const int g = lane >> 2;
    const int q = lane & 3;

    const uint32_t aoff = (uint32_t)(warp_m*32 + (lane & 15)) * PITCH
                        + ((lane >> 4) & 1) * 16;
    const uint32_t boff = ATILE
                        + (uint32_t)(warp_n*64 + (lane & 7) + ((lane >> 4) & 1)*8) * PITCH
                        + ((lane >> 3) & 1) * 16;

    float acc[2][8][4];
    #pragma unroll
    for (int m = 0; m < 2; m++)
        #pragma unroll
        for (int n = 0; n < 8; n++)
            #pragma unroll
            for (int r = 0; r < 4; r++) acc[m][n][r] = 0.0f;

    const int nch = K >> 6;      // chunks of 64

    // loader: A 1024 + B 2048 transfers of 16B (6 per thread)
    auto issue = [&](uint32_t dstbase, int k0) {
        #pragma unroll
        for (int i = 0; i < 2; i++) {
            int v = i*512 + tid;
            int row = v >> 3, seg = v & 7;
            cp16(dstbase + (uint32_t)row*PITCH + seg*16,
                 A + (size_t)(mbase+row)*K + k0 + seg*8);
        }
        #pragma unroll
        for (int i = 0; i < 4; i++) {
            int v = i*512 + tid;
            int row = v >> 3, seg = v & 7;
            cp16(dstbase + ATILE + (uint32_t)row*PITCH + seg*16,
                 Bt + (size_t)(nbase+row)*K + k0 + seg*8);
        }
    };

    issue(sb, 0);
    CP_COMMIT();

    for (int it = 0; it < nch; it++) {
        if (it + 1 < nch) {
            issue(sb + ((it+1) & 1) * BUFB, (it+1) << 6);
            CP_COMMIT();
            CP_WAIT1();
        } else {
            CP_WAIT0();
        }
        __syncthreads();

        const uint32_t bufu = sb + (it & 1) * BUFB;

        #pragma unroll
        for (int ks = 0; ks < 64; ks += 16) {
            uint32_t ar[2][4], bh[8][2];
            #pragma unroll
            for (int m = 0; m < 2; m++) {
                uint32_t ad = bufu + aoff + m*(16*PITCH) + ks*2;
                LDSM4(ar[m][0], ar[m][1], ar[m][2], ar[m][3], ad);
            }
            #pragma unroll
            for (int n2 = 0; n2 < 4; n2++) {
                uint32_t bd = bufu + boff + (uint32_t)n2*(16*PITCH) + ks*2;
                uint32_t r0, r1, r2, r3;
                LDSM4(r0, r1, r2, r3, bd);
                bh[n2*2][0] = r0; bh[n2*2][1] = r1;
                bh[n2*2+1][0] = r2; bh[n2*2+1][1] = r3;
            }
            #pragma unroll
            for (int m = 0; m < 2; m++)
                #pragma unroll
                for (int n = 0; n < 8; n++)
                    MMA_F32(acc[m][n], ar[m], bh[n]);
        }
        __syncthreads();
    }

    // epilogue: two 128-col halves staged through smem
    float* Cs = (float*)smem;   // [128][132]
    #pragma unroll
    for (int half = 0; half < 2; half++) {
        if ((warp_n >> 1) == half) {
            int cb = (warp_n & 1) * 64;
            #pragma unroll
            for (int m = 0; m < 2; m++) {
                int r0 = warp_m*32 + m*16 + g;
                #pragma unroll
                for (int n = 0; n < 8; n++) {
                    int col = cb + n*8 + 2*q;
                    Cs[r0*132 + col]       = acc[m][n][0];
                    Cs[r0*132 + col + 1]   = acc[m][n][1];
                    Cs[(r0+8)*132 + col]   = acc[m][n][2];
                    Cs[(r0+8)*132 + col+1] = acc[m][n][3];
                }
            }
        }
        __syncthreads();

        const int nb = nbase + half*128;
        if (EPI == 1) {
            #pragma unroll
            for (int i = 0; i < 8; i++) {
                int u = tid + i*512;
                int row = u >> 5, c4 = (u & 31) * 4;
                int col = nb + c4;
                float v0 = Cs[row*132 + c4 + 0] + bias[col];
                float v1 = Cs[row*132 + c4 + 1] + bias[col+1];
                float v2 = Cs[row*132 + c4 + 2] + bias[col+2];
                float v3 = Cs[row*132 + c4 + 3] + bias[col+3];
                v0 = fmaxf(v0, 0.f); v1 = fmaxf(v1, 0.f);
                v2 = fmaxf(v2, 0.f); v3 = fmaxf(v3, 0.f);
                uint2 hv;
                hv.x = pack2(v0, v1);
                hv.y = pack2(v2, v3);
                *(uint2*)(Ch + (size_t)(mbase+row)*N + col) = hv;
            }
        } else if ((N & 3) == 0) {
            #pragma unroll
            for (int i = 0; i < 8; i++) {
                int u = tid + i*512;
                int row = u >> 5, c4 = (u & 31) * 4;
                int col = nb + c4;
                float v0 = Cs[row*132 + c4 + 0];
                float v1 = Cs[row*132 + c4 + 1];
                float v2 = Cs[row*132 + c4 + 2];
                float v3 = Cs[row*132 + c4 + 3];
                if (bias) { v0 += bias[col]; v1 += bias[col+1]; v2 += bias[col+2]; v3 += bias[col+3]; }
                if (EPI == 2) {
                    const float4 rv = *(const float4*)(res + (size_t)(mbase+row)*N + col);
                    v0 += rv.x; v1 += rv.y; v2 += rv.z; v3 += rv.w;
                }
                *(float4*)(C + (size_t)(mbase+row)*N + col) = make_float4(v0, v1, v2, v3);
            }
        } else {
            // ragged-N path (LM head). One warp covers one row-half per iter.
            #pragma unroll
            for (int i = 0; i < 8; i++) {
                int u = tid + i*512;
                int row = u >> 5, c4 = (u & 31) * 4;
                float* crow = C + (size_t)(mbase+row)*N;
                float v[4];
                #pragma unroll
                for (int j = 0; j < 4; j++) {
                    int col = nb + c4 + j;
                    if (col < N) {
                        float vv = Cs[row*132 + c4 + j];
                        if (bias) vv += bias[col];
                        crow[col] = vv;
                        v[j] = vv;
                    } else {
                        v[j] = -1e30f;
                    }
                }
                if (EPI == 0 && part != nullptr) {
                    // warp-level logsumexp partial for this row's 128 cols
                    float lm = fmaxf(fmaxf(v[0], v[1]), fmaxf(v[2], v[3]));
                    #pragma unroll
                    for (int o2 = 16; o2 > 0; o2 >>= 1)
                        lm = fmaxf(lm, __shfl_xor_sync(0xffffffffu, lm, o2));
                    float ps = 0.0f;
                    #pragma unroll
                    for (int j = 0; j < 4; j++)
                        if (nb + c4 + j < N) ps += __expf(v[j] - lm);
                    #pragma unroll
                    for (int o2 = 16; o2 > 0; o2 >>= 1)
                        ps += __shfl_xor_sync(0xffffffffu, ps, o2);
                    if (lane == 0)
                        part[(size_t)(mbase+row)*NT2LM + blockIdx.y*2 + half]
                            = make_float2(lm, ps);
                }
            }
        }
        __syncthreads();
    }
}

// ---------------------------------------------------------------------------
// Tiled transpose to fp16: in [K,N] -> out [Npad,K], zero-pad rows >= N
// ---------------------------------------------------------------------------
__global__ __launch_bounds__(256) void tp_kernel(
    const float* __restrict__ in, __half* __restrict__ out,
    int K, int N, int Npad, size_t inStride, size_t outStride)
{
    __shared__ float t[32][33];
    const float* ip = in + blockIdx.z * inStride;
    __half* op = out + blockIdx.z * outStride;
    int n0 = blockIdx.x * 32, k0 = blockIdx.y * 32;
    int tx = threadIdx.x & 31, ty = threadIdx.x >> 5;
    #pragma unroll
    for (int j = ty; j < 32; j += 8) {
        int k = k0 + j, n = n0 + tx;
        t[j][tx] = (k < K && n < N) ? ip[(size_t)k * N + n] : 0.0f;
    }
    __syncthreads();
    #pragma unroll
    for (int j = ty; j < 32; j += 8) {
        int n = n0 + j, k = k0 + tx;
        if (n < Npad && k < K)
            op[(size_t)n * K + k] = __float2half_rn(t[tx][j]);
    }
}

// ---------------------------------------------------------------------------
// Elementwise fp16 quantize (LM-head input)
// ---------------------------------------------------------------------------
__global__ __launch_bounds__(256) void tohalf_kernel(
    const float* __restrict__ x, __half* __restrict__ xh)
{
    size_t i = ((size_t)blockIdx.x * 256 + threadIdx.x) * 4;
    float4 v = *(const float4*)(x + i);
    uint2 hv;
    hv.x = pack2(v.x, v.y);
    hv.y = pack2(v.z, v.w);
    *(uint2*)(xh + i) = hv;
}

// ---------------------------------------------------------------------------
// Embedding
// ---------------------------------------------------------------------------
__global__ __launch_bounds__(256) void embed_kernel(
    const int* __restrict__ idx, const float* __restrict__ tok,
    const float* __restrict__ pos, float* __restrict__ x)
{
    int row = blockIdx.x;
    int t   = row & (TT - 1);
    int id  = idx[row];
    const float4* tp = (const float4*)(tok + (size_t)id * DD);
    const float4* pp = (const float4*)(pos + (size_t)t  * DD);
    float4*       xp = (float4*)(x + (size_t)row * DD);
    int i = threadIdx.x;
    float4 a = tp[i], b = pp[i];
    a.x += b.x; a.y += b.y; a.z += b.z; a.w += b.w;
    xp[i] = a;
}

// ---------------------------------------------------------------------------
// LayerNorm -> plain fp16 output
// ---------------------------------------------------------------------------
__global__ __launch_bounds__(256) void ln_kernel(
    const float* __restrict__ x, const float* __restrict__ g,
    const float* __restrict__ b, __half* __restrict__ oh)
{
    __shared__ float s1[256];
    __shared__ float s2[256];
    int row = blockIdx.x;
    int tid = threadIdx.x;
    float4 v = ((const float4*)(x + (size_t)row * DD))[tid];
    float s  = v.x + v.y + v.z + v.w;
    float ss = v.x*v.x + v.y*v.y + v.z*v.z + v.w*v.w;
    s1[tid] = s; s2[tid] = ss;
    __syncthreads();
    for (int o = 128; o > 0; o >>= 1) {
        if (tid < o) { s1[tid] += s1[tid+o]; s2[tid] += s2[tid+o]; }
        __syncthreads();
    }
    float mu   = s1[0] * (1.0f / DD);
    float var  = s2[0] * (1.0f / DD) - mu * mu;
    float rstd = rsqrtf(var + 1e-5f);
    float4 gv = ((const float4*)g)[tid];
    float4 bv = ((const float4*)b)[tid];
    float o0 = (v.x - mu) * rstd * gv.x + bv.x;
    float o1 = (v.y - mu) * rstd * gv.y + bv.y;
    float o2 = (v.z - mu) * rstd * gv.z + bv.z;
    float o3 = (v.w - mu) * rstd * gv.w + bv.w;
    uint2 hv;
    hv.x = pack2(o0, o1);
    hv.y = pack2(o2, o3);
    *(uint2*)(oh + (size_t)row * DD + tid * 4) = hv;
}

// ---------------------------------------------------------------------------
// Tensor-core flash attention (unchanged from R11/R12).
// ---------------------------------------------------------------------------
#define APITCH 144

__global__ __launch_bounds__(128) void attn_kernel(
    const float* __restrict__ qkv, __half* __restrict__ yh)
{
    __shared__ __align__(16) char sm[3 * 64 * APITCH];
    char* Qs = sm;
    char* Ks = sm + 64*APITCH;
    char* Vs = sm + 2*64*APITCH;

    const int tid  = threadIdx.x;
    const int wid  = tid >> 5;
    const int lane = tid & 31;
    const int g = lane >> 2;
    const int q = lane & 3;
    const int bh = blockIdx.x;
    const int b  = bh >> 4;
    const int h  = bh & (HH - 1);
    const int qbase = blockIdx.y * 64;

    {
        int row = tid >> 1;
        int c0  = (tid & 1) * 32;
        const float* src = qkv + (size_t)(b*TT + qbase + row)*(3*DD) + h*HDIM + c0;
        char* dp = Qs + row*APITCH + c0*2;
        #pragma unroll
        for (int j = 0; j < 4; j++) {
            float4 v0 = *(const float4*)(src + j*8);
            float4 v1 = *(const float4*)(src + j*8 + 4);
            uint4 o;
            o.x = pack2(v0.x, v0.y); o.y = pack2(v0.z, v0.w);
            o.z = pack2(v1.x, v1.y); o.w = pack2(v1.z, v1.w);
            *(uint4*)(dp + j*16) = o;
        }
    }
    __syncthreads();

    uint32_t qa[4][4];
    {
        uint32_t qaddr = smem_u32(Qs) + (uint32_t)(wid*16 + (lane & 15))*APITCH
                       + ((lane >> 4) & 1) * 16;
        #pragma unroll
        for (int c = 0; c < 4; c++)
            LDSM4(qa[c][0], qa[c][1], qa[c][2], qa[c][3], qaddr + c*32);
    }

    const int qrow0 = qbase + wid*16 + g;
    const int qrow1 = qrow0 + 8;

    float m0 = -1e30f, m1 = -1e30f, l0 = 0.0f, l1 = 0.0f;
    float oacc[8][4];
    #pragma unroll
    for (int n = 0; n < 8; n++)
        #pragma unroll
        for (int r = 0; r < 4; r++) oacc[n][r] = 0.0f;

    const uint32_t kfr = smem_u32(Ks) + (uint32_t)((lane & 7) + ((lane >> 4) & 1)*8)*APITCH
                       + ((lane >> 3) & 1) * 16;
    const uint32_t vfr = smem_u32(Vs) + (uint32_t)((lane & 7) + ((lane >> 3) & 1)*8)*APITCH
                       + ((lane >> 4) & 1) * 16;

    const int ntiles = blockIdx.y + 1;
    for (int kt = 0; kt < ntiles; kt++) {
        const int kbase = kt * 64;
        __syncthreads();
        {
            int row = tid >> 1;
            int c0  = (tid & 1) * 32;
            const float* sk = qkv + (size_t)(b*TT + kbase + row)*(3*DD) + DD   + h*HDIM + c0;
            const float* sv = qkv + (size_t)(b*TT + kbase + row)*(3*DD) + 2*DD + h*HDIM + c0;
            char* dk = Ks + row*APITCH + c0*2;
            char* dv = Vs + row*APITCH + c0*2;
            #pragma unroll
            for (int j = 0; j < 4; j++) {
                float4 v0 = *(const float4*)(sk + j*8);
                float4 v1 = *(const float4*)(sk + j*8 + 4);
                uint4 o;
                o.x = pack2(v0.x, v0.y); o.y = pack2(v0.z, v0.w);
                o.z = pack2(v1.x, v1.y); o.w = pack2(v1.z, v1.w);
                *(uint4*)(dk + j*16) = o;
                v0 = *(const float4*)(sv + j*8);
                v1 = *(const float4*)(sv + j*8 + 4);
                o.x = pack2(v0.x, v0.y); o.y = pack2(v0.z, v0.w);
                o.z = pack2(v1.x, v1.y); o.w = pack2(v1.z, v1.w);
                *(uint4*)(dv + j*16) = o;
            }
        }
        __syncthreads();

        float s[8][4];
        #pragma unroll
        for (int n = 0; n < 8; n++)
            #pragma unroll
            for (int r = 0; r < 4; r++) s[n][r] = 0.0f;
        #pragma unroll
        for (int kc = 0; kc < 4; kc++) {
            #pragma unroll
            for (int n2 = 0; n2 < 4; n2++) {
                uint32_t r0, r1, r2, r3;
                LDSM4(r0, r1, r2, r3, kfr + (uint32_t)n2*(16*APITCH) + kc*32);
                uint32_t kb0[2] = {r0, r1};
                uint32_t kb1[2] = {r2, r3};
                MMA_F32(s[n2*2],   qa[kc], kb0);
                MMA_F32(s[n2*2+1], qa[kc], kb1);
            }
        }

        #pragma unroll
        for (int n = 0; n < 8; n++) {
            int k0 = kbase + n*8 + 2*q;
            s[n][0] = (k0     <= qrow0) ? s[n][0]*SCALE_ATT : -1e30f;
            s[n][1] = (k0 + 1 <= qrow0) ? s[n][1]*SCALE_ATT : -1e30f;
            s[n][2] = (k0     <= qrow1) ? s[n][2]*SCALE_ATT : -1e30f;
            s[n][3] = (k0 + 1 <= qrow1) ? s[n][3]*SCALE_ATT : -1e30f;
        }

        float mx0 = -1e30f, mx1 = -1e30f;
        #pragma unroll
        for (int n = 0; n < 8; n++) {
            mx0 = fmaxf(mx0, fmaxf(s[n][0], s[n][1]));
            mx1 = fmaxf(mx1, fmaxf(s[n][2], s[n][3]));
        }
        mx0 = fmaxf(mx0, __shfl_xor_sync(0xffffffffu, mx0, 1));
        mx0 = fmaxf(mx0, __shfl_xor_sync(0xffffffffu, mx0, 2));
        mx1 = fmaxf(mx1, __shfl_xor_sync(0xffffffffu, mx1, 1));
        mx1 = fmaxf(mx1, __shfl_xor_sync(0xffffffffu, mx1, 2));

        float nm0 = fmaxf(m0, mx0), nm1 = fmaxf(m1, mx1);
        float cor0 = __expf(m0 - nm0), cor1 = __expf(m1 - nm1);
        m0 = nm0; m1 = nm1;
        l0 *= cor0; l1 *= cor1;
        #pragma unroll
        for (int n = 0; n < 8; n++) {
            oacc[n][0] *= cor0; oacc[n][1] *= cor0;
            oacc[n][2] *= cor1; oacc[n][3] *= cor1;
        }

        float sum0 = 0.0f, sum1 = 0.0f;
        #pragma unroll
        for (int n = 0; n < 8; n++) {
            s[n][0] = __expf(s[n][0] - nm0); sum0 += s[n][0];
            s[n][1] = __expf(s[n][1] - nm0); sum0 += s[n][1];
            s[n][2] = __expf(s[n][2] - nm1); sum1 += s[n][2];
            s[n][3] = __expf(s[n][3] - nm1); sum1 += s[n][3];
        }
        sum0 += __shfl_xor_sync(0xffffffffu, sum0, 1);
        sum0 += __shfl_xor_sync(0xffffffffu, sum0, 2);
        sum1 += __shfl_xor_sync(0xffffffffu, sum1, 1);
        sum1 += __shfl_xor_sync(0xffffffffu, sum1, 2);
        l0 += sum0; l1 += sum1;

        #pragma unroll
        for (int kc = 0; kc < 4; kc++) {
            uint32_t pa[4];
            pa[0] = pack2(s[2*kc][0],   s[2*kc][1]);
            pa[1] = pack2(s[2*kc][2],   s[2*kc][3]);
            pa[2] = pack2(s[2*kc+1][0], s[2*kc+1][1]);
            pa[3] = pack2(s[2*kc+1][2], s[2*kc+1][3]);
            #pragma unroll
            for (int n2 = 0; n2 < 4; n2++) {
                uint32_t r0, r1, r2, r3;
                LDSM4T(r0, r1, r2, r3, vfr + (uint32_t)kc*(16*APITCH) + n2*32);
                uint32_t vb0[2] = {r0, r1};
                uint32_t vb1[2] = {r2, r3};
                MMA_F32(oacc[n2*2],   pa, vb0);
                MMA_F32(oacc[n2*2+1], pa, vb1);
            }
        }
    }

    float inv0 = 1.0f / l0, inv1 = 1.0f / l1;
    size_t base0 = (size_t)(b*TT + qrow0) * DD + h*HDIM;
    size_t base1 = base0 + (size_t)8 * DD;
    #pragma unroll
    for (int n = 0; n < 8; n++) {
        int col = n*8 + 2*q;
        *(uint32_t*)(yh + base0 + col) = pack2(oacc[n][0]*inv0, oacc[n][1]*inv0);
        *(uint32_t*)(yh + base1 + col) = pack2(oacc[n][2]*inv1, oacc[n][3]*inv1);
    }
}

// ---------------------------------------------------------------------------
// NLL from logsumexp partials (394 per row) + gathered target logit
// ---------------------------------------------------------------------------
__global__ __launch_bounds__(128) void nll_kernel(
    const float2* __restrict__ part, const float* __restrict__ logits,
    const int* __restrict__ tgt, float* __restrict__ nll)
{
    __shared__ float rm[128];
    __shared__ float rs[128];
    int row = blockIdx.x;
    int tid = threadIdx.x;
    const float2* pr = part + (size_t)row * NT2LM;

    float m = -1e30f, s = 0.0f;
    for (int i = tid; i < NT2LM; i += 128) {
        float2 p = pr[i];
        float M = fmaxf(m, p.x);
        s = s * __expf(m - M) + p.y * __expf(p.x - M);
        m = M;
    }
    rm[tid] = m; rs[tid] = s;
    __syncthreads();
    for (int o = 64; o > 0; o >>= 1) {
        if (tid < o) {
            float m2 = rm[tid + o], s2 = rs[tid + o];
            float M = fmaxf(rm[tid], m2);
            rs[tid] = rs[tid] * __expf(rm[tid] - M) + s2 * __expf(m2 - M);
            rm[tid] = M;
        }
        __syncthreads();
    }
    if (tid == 0) {
        float lse = rm[0] + logf(rs[0]);
        int tg = tgt[row];
        nll[row] = (tg != 0) ? (lse - logits[(size_t)row * VV + tg]) : 0.0f;
    }
}

__global__ __launch_bounds__(256) void loss_kernel(
    const float* __restrict__ nll, const int* __restrict__ tgt,
    float* __restrict__ out)
{
    __shared__ float s[256];
    __shared__ float c[256];
    int tid = threadIdx.x;
    float sv = 0.0f, cv = 0.0f;
    for (int i = tid; i < ROWS; i += 256) {
        sv += nll[i];
        cv += (tgt[i] != 0) ? 1.0f : 0.0f;
    }
    s[tid] = sv; c[tid] = cv; __syncthreads();
    for (int o = 128; o > 0; o >>= 1) {
        if (tid < o) { s[tid] += s[tid+o]; c[tid] += c[tid+o]; }
        __syncthreads();
    }
    if (tid == 0) out[0] = s[0] / fmaxf(c[0], 1.0f);
}

// ---------------------------------------------------------------------------
// Launcher
// ---------------------------------------------------------------------------
extern "C" void kernel_launch(void* const* d_in, const int* in_sizes, int n_in,
                              void* d_out, int out_size)
{
    const int*   idx   = (const int*)  d_in[0];
    const int*   tgt   = (const int*)  d_in[1];
    const float* tok   = (const float*)d_in[2];
    const float* pos   = (const float*)d_in[3];
    const float* ln1g  = (const float*)d_in[4];
    const float* ln1b  = (const float*)d_in[5];
    const float* wqkv  = (const float*)d_in[6];
    const float* bqkv  = (const float*)d_in[7];
    const float* wproj = (const float*)d_in[8];
    const float* bproj = (const float*)d_in[9];
    const float* ln2g  = (const float*)d_in[10];
    const float* ln2b  = (const float*)d_in[11];
    const float* w1    = (const float*)d_in[12];
    const float* b1    = (const float*)d_in[13];
    const float* w2    = (const float*)d_in[14];
    const float* b2    = (const float*)d_in[15];
    const float* lmw   = (const float*)d_in[16];

    float *px, *pqkv, *pnll;
    float2 *ppart;
    __half *ph, *py, *pm, *pxh;
    __half *pwqkv, *pwproj, *pw1, *pw2, *plmw;
    cudaGetSymbolAddress((void**)&px,    g_x);
    cudaGetSymbolAddress((void**)&pqkv,  g_qkv);
    cudaGetSymbolAddress((void**)&pnll,  g_nll);
    cudaGetSymbolAddress((void**)&ppart, g_part);
    cudaGetSymbolAddress((void**)&ph,    g_h);
    cudaGetSymbolAddress((void**)&py,    g_y);
    cudaGetSymbolAddress((void**)&pm,    g_m);
    cudaGetSymbolAddress((void**)&pxh,   g_xh);
    cudaGetSymbolAddress((void**)&pwqkv, g_wqkvT);
    cudaGetSymbolAddress((void**)&pwproj,g_wprojT);
    cudaGetSymbolAddress((void**)&pw1,   g_w1T);
    cudaGetSymbolAddress((void**)&pw2,   g_w2T);
    cudaGetSymbolAddress((void**)&plmw,  g_lmwT);

    cudaFuncSetAttribute((const void*)hgemm_kernel<0>,
                         cudaFuncAttributeMaxDynamicSharedMemorySize, SMEM_DYN);
    cudaFuncSetAttribute((const void*)hgemm_kernel<1>,
                         cudaFuncAttributeMaxDynamicSharedMemorySize, SMEM_DYN);
    cudaFuncSetAttribute((const void*)hgemm_kernel<2>,
                         cudaFuncAttributeMaxDynamicSharedMemorySize, SMEM_DYN);

    float* out = (float*)d_out;

    // weight transposes to fp16 (graph-captured each launch)
    tp_kernel<<<dim3(3*DD/32, DD/32, LL), 256>>>(
        wqkv, pwqkv, DD, 3*DD, 3*DD, (size_t)DD*3*DD, (size_t)3*DD*DD);
    tp_kernel<<<dim3(DD/32, DD/32, LL), 256>>>(
        wproj, pwproj, DD, DD, DD, (size_t)DD*DD, (size_t)DD*DD);
    tp_kernel<<<dim3(4*DD/32, DD/32, LL), 256>>>(
        w1, pw1, DD, 4*DD, 4*DD, (size_t)DD*4*DD, (size_t)4*DD*DD);
    tp_kernel<<<dim3(DD/32, 4*DD/32, LL), 256>>>(
        w2, pw2, 4*DD, DD, DD, (size_t)4*DD*DD, (size_t)DD*4*DD);
    tp_kernel<<<dim3(VPAD/32, DD/32, 1), 256>>>(
        lmw, plmw, DD, VV, VPAD, 0, 0);

    embed_kernel<<<ROWS, 256>>>(idx, tok, pos, px);

    for (int l = 0; l < LL; l++) {
        ln_kernel<<<ROWS, 256>>>(px, ln1g + (size_t)l*DD, ln1b + (size_t)l*DD, ph);
        hgemm_kernel<0><<<dim3(ROWS/128, 3*DD/256), 512, SMEM_DYN>>>(
            ROWS, 3*DD, DD, ph, pwqkv + (size_t)l*3*DD*DD,
            bqkv + (size_t)l*3*DD, nullptr, pqkv, nullptr, nullptr);
        attn_kernel<<<dim3(BB*HH, TT/64), 128>>>(pqkv, py);
        hgemm_kernel<2><<<dim3(ROWS/128, DD/256), 512, SMEM_DYN>>>(
            ROWS, DD, DD, py, pwproj + (size_t)l*DD*DD,
            bproj + (size_t)l*DD, px, px, nullptr, nullptr);
        ln_kernel<<<ROWS, 256>>>(px, ln2g + (size_t)l*DD, ln2b + (size_t)l*DD, ph);
        hgemm_kernel<1><<<dim3(ROWS/128, 4*DD/256), 512, SMEM_DYN>>>(
            ROWS, 4*DD, DD, ph, pw1 + (size_t)l*4*DD*DD,
            b1 + (size_t)l*4*DD, nullptr, nullptr, pm, nullptr);
        hgemm_kernel<2><<<dim3(ROWS/128, DD/256), 512, SMEM_DYN>>>(
            ROWS, DD, 4*DD, pm, pw2 + (size_t)l*DD*4*DD,
            b2 + (size_t)l*DD, px, px, nullptr, nullptr);
    }

    // quantize residual, logits = x @ lm_w (+ fused logsumexp partials)
    tohalf_kernel<<<ROWS, 256>>>(px, pxh);
    hgemm_kernel<0><<<dim3(ROWS/128, VPAD/256), 512, SMEM_DYN>>>(
        ROWS, VV, DD, pxh, plmw, nullptr, nullptr, out, nullptr, ppart);

    // loss from partials
    nll_kernel<<<ROWS, 128>>>(ppart, out, tgt, pnll);
    size_t nlog = (size_t)ROWS * VV;
    if ((size_t)out_size > nlog) {
        loss_kernel<<<1, 256>>>(pnll, tgt, out + nlog);
    }
}

// round 14
// speedup vs baseline: 3.3096x; 1.0958x over previous
#include <cuda_runtime.h>
#include <cuda_fp16.h>
#include <math.h>
#include <stdint.h>

// Problem constants
#define BB 4
#define TT 1024
#define DD 1024
#define HH 16
#define HDIM 64
#define LL 8
#define VV 50257
#define VPAD 50432              // multiple of 256
#define NT2LM ((VPAD/256)*2)    // 394 logsumexp partials per row
#define ROWS (BB*TT)            // 4096
#define SCALE_ATT 0.07216878364870322f  // 1/sqrt(192)

// ---------------------------------------------------------------------------
// Scratch (static device globals; no runtime allocation)
// ---------------------------------------------------------------------------
__device__ float g_x   [ (size_t)ROWS * DD ];
__device__ float g_nll [ ROWS ];
__device__ float2 g_part[ (size_t)ROWS * NT2LM ];
// plain fp16 activations
__device__ __half g_qkvh[ (size_t)ROWS * 3 * DD ];
__device__ __half g_h  [ (size_t)ROWS * DD ];
__device__ __half g_y  [ (size_t)ROWS * DD ];
__device__ __half g_m  [ (size_t)ROWS * 4 * DD ];
__device__ __half g_xh [ (size_t)ROWS * DD ];
// fp16 transposed weights ([N,K] row-major)
__device__ __half g_wqkvT [ (size_t)LL * 3*DD * DD ];
__device__ __half g_wprojT[ (size_t)LL * DD * DD ];
__device__ __half g_w1T   [ (size_t)LL * 4*DD * DD ];
__device__ __half g_w2T   [ (size_t)LL * DD * 4*DD ];
__device__ __half g_lmwT  [ (size_t)VPAD * DD ];

// ---------------------------------------------------------------------------
// helpers
// ---------------------------------------------------------------------------
__device__ __forceinline__ uint32_t smem_u32(const void* p) {
    uint32_t a;
    asm("{ .reg .u64 t; cvta.to.shared.u64 t, %1; cvt.u32.u64 %0, t; }"
        : "=r"(a) : "l"(p));
    return a;
}
__device__ __forceinline__ uint32_t pack2(float x, float y) {
    __half hx = __float2half_rn(x);
    __half hy = __float2half_rn(y);
    return (uint32_t)__half_as_ushort(hx) | ((uint32_t)__half_as_ushort(hy) << 16);
}

#define MMA_F32(d, a, b) \
    asm volatile("mma.sync.aligned.m16n8k16.row.col.f32.f16.f16.f32 " \
        "{%0,%1,%2,%3}, {%4,%5,%6,%7}, {%8,%9}, {%0,%1,%2,%3};" \
        : "+f"((d)[0]), "+f"((d)[1]), "+f"((d)[2]), "+f"((d)[3]) \
        : "r"((a)[0]), "r"((a)[1]), "r"((a)[2]), "r"((a)[3]), \
          "r"((b)[0]), "r"((b)[1]))

#define LDSM4(r0, r1, r2, r3, addr) \
    asm volatile("ldmatrix.sync.aligned.m8n8.x4.shared.b16 {%0,%1,%2,%3}, [%4];" \
        : "=r"(r0), "=r"(r1), "=r"(r2), "=r"(r3) : "r"(addr))

#define LDSM4T(r0, r1, r2, r3, addr) \
    asm volatile("ldmatrix.sync.aligned.m8n8.x4.trans.shared.b16 {%0,%1,%2,%3}, [%4];" \
        : "=r"(r0), "=r"(r1), "=r"(r2), "=r"(r3) : "r"(addr))

__device__ __forceinline__ void cp16(uint32_t d, const void* g) {
    asm volatile("cp.async.cg.shared.global [%0], [%1], 16;" :: "r"(d), "l"(g));
}
#define CP_COMMIT() asm volatile("cp.async.commit_group;" ::: "memory")
#define CP_WAIT0()  asm volatile("cp.async.wait_group 0;" ::: "memory")
#define CP_WAIT1()  asm volatile("cp.async.wait_group 1;" ::: "memory")

// ---------------------------------------------------------------------------
// fp16 tensor GEMM: C[M,N] = A[M,K] @ Bt[N,K]^T (+bias)(+relu/+res)
// CTA tile 128x256, K-chunk 64, 2-stage cp.async, 512 threads.
// EPI: 0=bias->f32 (+opt lse partials), 1=bias+relu->fp16, 2=+res->f32,
//      3=bias->fp16.
// ---------------------------------------------------------------------------
#define PITCH 144
#define ATILE (128*PITCH)        // 18432
#define BTILE (256*PITCH)        // 36864
#define BUFB  (ATILE + BTILE)    // 55296
#define SMEM_DYN (2*BUFB)        // 110592

template<int EPI>
__global__ __launch_bounds__(512) void hgemm_kernel(
    int M, int N, int K,
    const __half* __restrict__ A, const __half* __restrict__ Bt,
    const float* __restrict__ bias, const float* __restrict__ res,
    float* __restrict__ C, __half* __restrict__ Ch,
    float2* __restrict__ part)
{
    extern __shared__ __align__(128) char smem[];
    const uint32_t sb = smem_u32(smem);
    const int tid  = threadIdx.x;
    const int wid  = tid >> 5;
    const int lane = tid & 31;
    const int mbase = blockIdx.x * 128;
    const int nbase = blockIdx.y * 256;
    const int warp_m = wid & 3;
    const int warp_n = wid >> 2;
    const int g = lane >> 2;
    const int q = lane & 3;

    const uint32_t aoff = (uint32_t)(warp_m*32 + (lane & 15)) * PITCH
                        + ((lane >> 4) & 1) * 16;
    const uint32_t boff = ATILE
                        + (uint32_t)(warp_n*64 + (lane & 7) + ((lane >> 4) & 1)*8) * PITCH
                        + ((lane >> 3) & 1) * 16;

    float acc[2][8][4];
    #pragma unroll
    for (int m = 0; m < 2; m++)
        #pragma unroll
        for (int n = 0; n < 8; n++)
            #pragma unroll
            for (int r = 0; r < 4; r++) acc[m][n][r] = 0.0f;

    const int nch = K >> 6;

    auto issue = [&](uint32_t dstbase, int k0) {
        #pragma unroll
        for (int i = 0; i < 2; i++) {
            int v = i*512 + tid;
            int row = v >> 3, seg = v & 7;
            cp16(dstbase + (uint32_t)row*PITCH + seg*16,
                 A + (size_t)(mbase+row)*K + k0 + seg*8);
        }
        #pragma unroll
        for (int i = 0; i < 4; i++) {
            int v = i*512 + tid;
            int row = v >> 3, seg = v & 7;
            cp16(dstbase + ATILE + (uint32_t)row*PITCH + seg*16,
                 Bt + (size_t)(nbase+row)*K + k0 + seg*8);
        }
    };

    issue(sb, 0);
    CP_COMMIT();

    for (int it = 0; it < nch; it++) {
        if (it + 1 < nch) {
            issue(sb + ((it+1) & 1) * BUFB, (it+1) << 6);
            CP_COMMIT();
            CP_WAIT1();
        } else {
            CP_WAIT0();
        }
        __syncthreads();

        const uint32_t bufu = sb + (it & 1) * BUFB;

        #pragma unroll
        for (int ks = 0; ks < 64; ks += 16) {
            uint32_t ar[2][4], bh[8][2];
            #pragma unroll
            for (int m = 0; m < 2; m++) {
                uint32_t ad = bufu + aoff + m*(16*PITCH) + ks*2;
                LDSM4(ar[m][0], ar[m][1], ar[m][2], ar[m][3], ad);
            }
            #pragma unroll
            for (int n2 = 0; n2 < 4; n2++) {
                uint32_t bd = bufu + boff + (uint32_t)n2*(16*PITCH) + ks*2;
                uint32_t r0, r1, r2, r3;
                LDSM4(r0, r1, r2, r3, bd);
                bh[n2*2][0] = r0; bh[n2*2][1] = r1;
                bh[n2*2+1][0] = r2; bh[n2*2+1][1] = r3;
            }
            #pragma unroll
            for (int m = 0; m < 2; m++)
                #pragma unroll
                for (int n = 0; n < 8; n++)
                    MMA_F32(acc[m][n], ar[m], bh[n]);
        }
        __syncthreads();
    }

    // epilogue: two 128-col halves staged through smem
    float* Cs = (float*)smem;   // [128][132]
    #pragma unroll
    for (int half = 0; half < 2; half++) {
        if ((warp_n >> 1) == half) {
            int cb = (warp_n & 1) * 64;
            #pragma unroll
            for (int m = 0; m < 2; m++) {
                int r0 = warp_m*32 + m*16 + g;
                #pragma unroll
                for (int n = 0; n < 8; n++) {
                    int col = cb + n*8 + 2*q;
                    Cs[r0*132 + col]       = acc[m][n][0];
                    Cs[r0*132 + col + 1]   = acc[m][n][1];
                    Cs[(r0+8)*132 + col]   = acc[m][n][2];
                    Cs[(r0+8)*132 + col+1] = acc[m][n][3];
                }
            }
        }
        __syncthreads();

        const int nb = nbase + half*128;
        if (EPI == 1 || EPI == 3) {
            #pragma unroll
            for (int i = 0; i < 8; i++) {
                int u = tid + i*512;
                int row = u >> 5, c4 = (u & 31) * 4;
                int col = nb + c4;
                float v0 = Cs[row*132 + c4 + 0] + bias[col];
                float v1 = Cs[row*132 + c4 + 1] + bias[col+1];
                float v2 = Cs[row*132 + c4 + 2] + bias[col+2];
                float v3 = Cs[row*132 + c4 + 3] + bias[col+3];
                if (EPI == 1) {
                    v0 = fmaxf(v0, 0.f); v1 = fmaxf(v1, 0.f);
                    v2 = fmaxf(v2, 0.f); v3 = fmaxf(v3, 0.f);
                }
                uint2 hv;
                hv.x = pack2(v0, v1);
                hv.y = pack2(v2, v3);
                *(uint2*)(Ch + (size_t)(mbase+row)*N + col) = hv;
            }
        } else if ((N & 3) == 0) {
            #pragma unroll
            for (int i = 0; i < 8; i++) {
                int u = tid + i*512;
                int row = u >> 5, c4 = (u & 31) * 4;
                int col = nb + c4;
                float v0 = Cs[row*132 + c4 + 0];
                float v1 = Cs[row*132 + c4 + 1];
                float v2 = Cs[row*132 + c4 + 2];
                float v3 = Cs[row*132 + c4 + 3];
                if (bias) { v0 += bias[col]; v1 += bias[col+1]; v2 += bias[col+2]; v3 += bias[col+3]; }
                if (EPI == 2) {
                    const float4 rv = *(const float4*)(res + (size_t)(mbase+row)*N + col);
                    v0 += rv.x; v1 += rv.y; v2 += rv.z; v3 += rv.w;
                }
                *(float4*)(C + (size_t)(mbase+row)*N + col) = make_float4(v0, v1, v2, v3);
            }
        } else {
            // ragged-N path (LM head)
            #pragma unroll
            for (int i = 0; i < 8; i++) {
                int u = tid + i*512;
                int row = u >> 5, c4 = (u & 31) * 4;
                float* crow = C + (size_t)(mbase+row)*N;
                float v[4];
                #pragma unroll
                for (int j = 0; j < 4; j++) {
                    int col = nb + c4 + j;
                    if (col < N) {
                        float vv = Cs[row*132 + c4 + j];
                        if (bias) vv += bias[col];
                        crow[col] = vv;
                        v[j] = vv;
                    } else {
                        v[j] = -1e30f;
                    }
                }
                if (EPI == 0 && part != nullptr) {
                    float lm = fmaxf(fmaxf(v[0], v[1]), fmaxf(v[2], v[3]));
                    #pragma unroll
                    for (int o2 = 16; o2 > 0; o2 >>= 1)
                        lm = fmaxf(lm, __shfl_xor_sync(0xffffffffu, lm, o2));
                    float ps = 0.0f;
                    #pragma unroll
                    for (int j = 0; j < 4; j++)
                        if (nb + c4 + j < N) ps += __expf(v[j] - lm);
                    #pragma unroll
                    for (int o2 = 16; o2 > 0; o2 >>= 1)
                        ps += __shfl_xor_sync(0xffffffffu, ps, o2);
                    if (lane == 0)
                        part[(size_t)(mbase+row)*NT2LM + blockIdx.y*2 + half]
                            = make_float2(lm, ps);
                }
            }
        }
        __syncthreads();
    }
}

// ---------------------------------------------------------------------------
// Tiled transpose to fp16: in [K,N] -> out [Npad,K], zero-pad rows >= N
// ---------------------------------------------------------------------------
__global__ __launch_bounds__(256) void tp_kernel(
    const float* __restrict__ in, __half* __restrict__ out,
    int K, int N, int Npad, size_t inStride, size_t outStride)
{
    __shared__ float t[32][33];
    const float* ip = in + blockIdx.z * inStride;
    __half* op = out + blockIdx.z * outStride;
    int n0 = blockIdx.x * 32, k0 = blockIdx.y * 32;
    int tx = threadIdx.x & 31, ty = threadIdx.x >> 5;
    #pragma unroll
    for (int j = ty; j < 32; j += 8) {
        int k = k0 + j, n = n0 + tx;
        t[j][tx] = (k < K && n < N) ? ip[(size_t)k * N + n] : 0.0f;
    }
    __syncthreads();
    #pragma unroll
    for (int j = ty; j < 32; j += 8) {
        int n = n0 + j, k = k0 + tx;
        if (n < Npad && k < K)
            op[(size_t)n * K + k] = __float2half_rn(t[tx][j]);
    }
}

// ---------------------------------------------------------------------------
// Elementwise fp16 quantize (LM-head input)
// ---------------------------------------------------------------------------
__global__ __launch_bounds__(256) void tohalf_kernel(
    const float* __restrict__ x, __half* __restrict__ xh)
{
    size_t i = ((size_t)blockIdx.x * 256 + threadIdx.x) * 4;
    float4 v = *(const float4*)(x + i);
    uint2 hv;
    hv.x = pack2(v.x, v.y);
    hv.y = pack2(v.z, v.w);
    *(uint2*)(xh + i) = hv;
}

// ---------------------------------------------------------------------------
// Embedding
// ---------------------------------------------------------------------------
__global__ __launch_bounds__(256) void embed_kernel(
    const int* __restrict__ idx, const float* __restrict__ tok,
    const float* __restrict__ pos, float* __restrict__ x)
{
    int row = blockIdx.x;
    int t   = row & (TT - 1);
    int id  = idx[row];
    const float4* tp = (const float4*)(tok + (size_t)id * DD);
    const float4* pp = (const float4*)(pos + (size_t)t  * DD);
    float4*       xp = (float4*)(x + (size_t)row * DD);
    int i = threadIdx.x;
    float4 a = tp[i], b = pp[i];
    a.x += b.x; a.y += b.y; a.z += b.z; a.w += b.w;
    xp[i] = a;
}

// ---------------------------------------------------------------------------
// LayerNorm -> plain fp16 output
// ---------------------------------------------------------------------------
__global__ __launch_bounds__(256) void ln_kernel(
    const float* __restrict__ x, const float* __restrict__ g,
    const float* __restrict__ b, __half* __restrict__ oh)
{
    __shared__ float s1[256];
    __shared__ float s2[256];
    int row = blockIdx.x;
    int tid = threadIdx.x;
    float4 v = ((const float4*)(x + (size_t)row * DD))[tid];
    float s  = v.x + v.y + v.z + v.w;
    float ss = v.x*v.x + v.y*v.y + v.z*v.z + v.w*v.w;
    s1[tid] = s; s2[tid] = ss;
    __syncthreads();
    for (int o = 128; o > 0; o >>= 1) {
        if (tid < o) { s1[tid] += s1[tid+o]; s2[tid] += s2[tid+o]; }
        __syncthreads();
    }
    float mu   = s1[0] * (1.0f / DD);
    float var  = s2[0] * (1.0f / DD) - mu * mu;
    float rstd = rsqrtf(var + 1e-5f);
    float4 gv = ((const float4*)g)[tid];
    float4 bv = ((const float4*)b)[tid];
    float o0 = (v.x - mu) * rstd * gv.x + bv.x;
    float o1 = (v.y - mu) * rstd * gv.y + bv.y;
    float o2 = (v.z - mu) * rstd * gv.z + bv.z;
    float o3 = (v.w - mu) * rstd * gv.w + bv.w;
    uint2 hv;
    hv.x = pack2(o0, o1);
    hv.y = pack2(o2, o3);
    *(uint2*)(oh + (size_t)row * DD + tid * 4) = hv;
}

// ---------------------------------------------------------------------------
// Tensor-core flash attention, fp16 qkv input, double-buffered cp.async K/V.
// Block = 128 threads (4 warps): one (b,h), 64-query tile. Grid (B*H, T/64).
// ---------------------------------------------------------------------------
#define APITCH 144
#define ATILE2 (64*APITCH)       // 9216

__global__ __launch_bounds__(128) void attn_kernel(
    const __half* __restrict__ qkv, __half* __restrict__ yh)
{
    __shared__ __align__(16) char sm[5 * ATILE2];   // Q | K0 K1 | V0 V1
    const uint32_t sbase = smem_u32(sm);

    const int tid  = threadIdx.x;
    const int wid  = tid >> 5;
    const int lane = tid & 31;
    const int g = lane >> 2;
    const int q = lane & 3;
    const int bh = blockIdx.x;
    const int b  = bh >> 4;
    const int h  = bh & (HH - 1);
    const int qbase = blockIdx.y * 64;

    // K/V tile loader (cp.async, 8 transfers per thread)
    auto issue = [&](int kt) {
        const int bsel = kt & 1;
        const int kbase = kt * 64;
        #pragma unroll
        for (int i = 0; i < 4; i++) {
            int v = i*128 + tid;
            int row = v >> 3, seg = v & 7;
            const __half* src = qkv + (size_t)(b*TT + kbase + row)*(3*DD)
                              + DD + h*HDIM + seg*8;
            uint32_t doff = (uint32_t)row*APITCH + seg*16;
            cp16(sbase + (1+bsel)*ATILE2 + doff, src);        // K
            cp16(sbase + (3+bsel)*ATILE2 + doff, src + DD);   // V
        }
    };

    // Q load (cp.async, group 0 together with tile 0)
    {
        #pragma unroll
        for (int i = 0; i < 4; i++) {
            int v = i*128 + tid;
            int row = v >> 3, seg = v & 7;
            cp16(sbase + (uint32_t)row*APITCH + seg*16,
                 qkv + (size_t)(b*TT + qbase + row)*(3*DD) + h*HDIM + seg*8);
        }
        issue(0);
        CP_COMMIT();
    }

    const int qrow0 = qbase + wid*16 + g;
    const int qrow1 = qrow0 + 8;

    uint32_t qa[4][4];
    float m0 = -1e30f, m1 = -1e30f, l0 = 0.0f, l1 = 0.0f;
    float oacc[8][4];
    #pragma unroll
    for (int n = 0; n < 8; n++)
        #pragma unroll
        for (int r = 0; r < 4; r++) oacc[n][r] = 0.0f;

    const uint32_t kfl = (uint32_t)((lane & 7) + ((lane >> 4) & 1)*8)*APITCH
                       + ((lane >> 3) & 1) * 16;
    const uint32_t vfl = (uint32_t)((lane & 7) + ((lane >> 3) & 1)*8)*APITCH
                       + ((lane >> 4) & 1) * 16;

    const int ntiles = blockIdx.y + 1;
    for (int kt = 0; kt < ntiles; kt++) {
        const int kbase = kt * 64;
        if (kt + 1 < ntiles) {
            issue(kt + 1);
            CP_COMMIT();
            CP_WAIT1();
        } else {
            CP_WAIT0();
        }
        __syncthreads();

        if (kt == 0) {
            uint32_t qaddr = sbase + (uint32_t)(wid*16 + (lane & 15))*APITCH
                           + ((lane >> 4) & 1) * 16;
            #pragma unroll
            for (int c = 0; c < 4; c++)
                LDSM4(qa[c][0], qa[c][1], qa[c][2], qa[c][3], qaddr + c*32);
        }

        const uint32_t kfr = sbase + (1 + (kt & 1))*ATILE2 + kfl;
        const uint32_t vfr = sbase + (3 + (kt & 1))*ATILE2 + vfl;

        float s[8][4];
        #pragma unroll
        for (int n = 0; n < 8; n++)
            #pragma unroll
            for (int r = 0; r < 4; r++) s[n][r] = 0.0f;
        #pragma unroll
        for (int kc = 0; kc < 4; kc++) {
            #pragma unroll
            for (int n2 = 0; n2 < 4; n2++) {
                uint32_t r0, r1, r2, r3;
                LDSM4(r0, r1, r2, r3, kfr + (uint32_t)n2*(16*APITCH) + kc*32);
                uint32_t kb0[2] = {r0, r1};
                uint32_t kb1[2] = {r2, r3};
                MMA_F32(s[n2*2],   qa[kc], kb0);
                MMA_F32(s[n2*2+1], qa[kc], kb1);
            }
        }

        #pragma unroll
        for (int n = 0; n < 8; n++) {
            int k0 = kbase + n*8 + 2*q;
            s[n][0] = (k0     <= qrow0) ? s[n][0]*SCALE_ATT : -1e30f;
            s[n][1] = (k0 + 1 <= qrow0) ? s[n][1]*SCALE_ATT : -1e30f;
            s[n][2] = (k0     <= qrow1) ? s[n][2]*SCALE_ATT : -1e30f;
            s[n][3] = (k0 + 1 <= qrow1) ? s[n][3]*SCALE_ATT : -1e30f;
        }

        float mx0 = -1e30f, mx1 = -1e30f;
        #pragma unroll
        for (int n = 0; n < 8; n++) {
            mx0 = fmaxf(mx0, fmaxf(s[n][0], s[n][1]));
            mx1 = fmaxf(mx1, fmaxf(s[n][2], s[n][3]));
        }
        mx0 = fmaxf(mx0, __shfl_xor_sync(0xffffffffu, mx0, 1));
        mx0 = fmaxf(mx0, __shfl_xor_sync(0xffffffffu, mx0, 2));
        mx1 = fmaxf(mx1, __shfl_xor_sync(0xffffffffu, mx1, 1));
        mx1 = fmaxf(mx1, __shfl_xor_sync(0xffffffffu, mx1, 2));

        float nm0 = fmaxf(m0, mx0), nm1 = fmaxf(m1, mx1);
        float cor0 = __expf(m0 - nm0), cor1 = __expf(m1 - nm1);
        m0 = nm0; m1 = nm1;
        l0 *= cor0; l1 *= cor1;
        #pragma unroll
        for (int n = 0; n < 8; n++) {
            oacc[n][0] *= cor0; oacc[n][1] *= cor0;
            oacc[n][2] *= cor1; oacc[n][3] *= cor1;
        }

        float sum0 = 0.0f, sum1 = 0.0f;
        #pragma unroll
        for (int n = 0; n < 8; n++) {
            s[n][0] = __expf(s[n][0] - nm0); sum0 += s[n][0];
            s[n][1] = __expf(s[n][1] - nm0); sum0 += s[n][1];
            s[n][2] = __expf(s[n][2] - nm1); sum1 += s[n][2];
            s[n][3] = __expf(s[n][3] - nm1); sum1 += s[n][3];
        }
        sum0 += __shfl_xor_sync(0xffffffffu, sum0, 1);
        sum0 += __shfl_xor_sync(0xffffffffu, sum0, 2);
        sum1 += __shfl_xor_sync(0xffffffffu, sum1, 1);
        sum1 += __shfl_xor_sync(0xffffffffu, sum1, 2);
        l0 += sum0; l1 += sum1;

        #pragma unroll
        for (int kc = 0; kc < 4; kc++) {
            uint32_t pa[4];
            pa[0] = pack2(s[2*kc][0],   s[2*kc][1]);
            pa[1] = pack2(s[2*kc][2],   s[2*kc][3]);
            pa[2] = pack2(s[2*kc+1][0], s[2*kc+1][1]);
            pa[3] = pack2(s[2*kc+1][2], s[2*kc+1][3]);
            #pragma unroll
            for (int n2 = 0; n2 < 4; n2++) {
                uint32_t r0, r1, r2, r3;
                LDSM4T(r0, r1, r2, r3, vfr + (uint32_t)kc*(16*APITCH) + n2*32);
                uint32_t vb0[2] = {r0, r1};
                uint32_t vb1[2] = {r2, r3};
                MMA_F32(oacc[n2*2],   pa, vb0);
                MMA_F32(oacc[n2*2+1], pa, vb1);
            }
        }
        __syncthreads();
    }

    float inv0 = 1.0f / l0, inv1 = 1.0f / l1;
    size_t base0 = (size_t)(b*TT + qrow0) * DD + h*HDIM;
    size_t base1 = base0 + (size_t)8 * DD;
    #pragma unroll
    for (int n = 0; n < 8; n++) {
        int col = n*8 + 2*q;
        *(uint32_t*)(yh + base0 + col) = pack2(oacc[n][0]*inv0, oacc[n][1]*inv0);
        *(uint32_t*)(yh + base1 + col) = pack2(oacc[n][2]*inv1, oacc[n][3]*inv1);
    }
}

// ---------------------------------------------------------------------------
// NLL from logsumexp partials + gathered target logit
// ---------------------------------------------------------------------------
__global__ __launch_bounds__(128) void nll_kernel(
    const float2* __restrict__ part, const float* __restrict__ logits,
    const int* __restrict__ tgt, float* __restrict__ nll)
{
    __shared__ float rm[128];
    __shared__ float rs[128];
    int row = blockIdx.x;
    int tid = threadIdx.x;
    const float2* pr = part + (size_t)row * NT2LM;

    float m = -1e30f, s = 0.0f;
    for (int i = tid; i < NT2LM; i += 128) {
        float2 p = pr[i];
        float M = fmaxf(m, p.x);
        s = s * __expf(m - M) + p.y * __expf(p.x - M);
        m = M;
    }
    rm[tid] = m; rs[tid] = s;
    __syncthreads();
    for (int o = 64; o > 0; o >>= 1) {
        if (tid < o) {
            float m2 = rm[tid + o], s2 = rs[tid + o];
            float M = fmaxf(rm[tid], m2);
            rs[tid] = rs[tid] * __expf(rm[tid] - M) + s2 * __expf(m2 - M);
            rm[tid] = M;
        }
        __syncthreads();
    }
    if (tid == 0) {
        float lse = rm[0] + logf(rs[0]);
        int tg = tgt[row];
        nll[row] = (tg != 0) ? (lse - logits[(size_t)row * VV + tg]) : 0.0f;
    }
}

__global__ __launch_bounds__(256) void loss_kernel(
    const float* __restrict__ nll, const int* __restrict__ tgt,
    float* __restrict__ out)
{
    __shared__ float s[256];
    __shared__ float c[256];
    int tid = threadIdx.x;
    float sv = 0.0f, cv = 0.0f;
    for (int i = tid; i < ROWS; i += 256) {
        sv += nll[i];
        cv += (tgt[i] != 0) ? 1.0f : 0.0f;
    }
    s[tid] = sv; c[tid] = cv; __syncthreads();
    for (int o = 128; o > 0; o >>= 1) {
        if (tid < o) { s[tid] += s[tid+o]; c[tid] += c[tid+o]; }
        __syncthreads();
    }
    if (tid == 0) out[0] = s[0] / fmaxf(c[0], 1.0f);
}

// ---------------------------------------------------------------------------
// Launcher
// ---------------------------------------------------------------------------
extern "C" void kernel_launch(void* const* d_in, const int* in_sizes, int n_in,
                              void* d_out, int out_size)
{
    const int*   idx   = (const int*)  d_in[0];
    const int*   tgt   = (const int*)  d_in[1];
    const float* tok   = (const float*)d_in[2];
    const float* pos   = (const float*)d_in[3];
    const float* ln1g  = (const float*)d_in[4];
    const float* ln1b  = (const float*)d_in[5];
    const float* wqkv  = (const float*)d_in[6];
    const float* bqkv  = (const float*)d_in[7];
    const float* wproj = (const float*)d_in[8];
    const float* bproj = (const float*)d_in[9];
    const float* ln2g  = (const float*)d_in[10];
    const float* ln2b  = (const float*)d_in[11];
    const float* w1    = (const float*)d_in[12];
    const float* b1    = (const float*)d_in[13];
    const float* w2    = (const float*)d_in[14];
    const float* b2    = (const float*)d_in[15];
    const float* lmw   = (const float*)d_in[16];

    float *px, *pnll;
    float2 *ppart;
    __half *pqkvh, *ph, *py, *pm, *pxh;
    __half *pwqkv, *pwproj, *pw1, *pw2, *plmw;
    cudaGetSymbolAddress((void**)&px,    g_x);
    cudaGetSymbolAddress((void**)&pnll,  g_nll);
    cudaGetSymbolAddress((void**)&ppart, g_part);
    cudaGetSymbolAddress((void**)&pqkvh, g_qkvh);
    cudaGetSymbolAddress((void**)&ph,    g_h);
    cudaGetSymbolAddress((void**)&py,    g_y);
    cudaGetSymbolAddress((void**)&pm,    g_m);
    cudaGetSymbolAddress((void**)&pxh,   g_xh);
    cudaGetSymbolAddress((void**)&pwqkv, g_wqkvT);
    cudaGetSymbolAddress((void**)&pwproj,g_wprojT);
    cudaGetSymbolAddress((void**)&pw1,   g_w1T);
    cudaGetSymbolAddress((void**)&pw2,   g_w2T);
    cudaGetSymbolAddress((void**)&plmw,  g_lmwT);

    cudaFuncSetAttribute((const void*)hgemm_kernel<0>,
                         cudaFuncAttributeMaxDynamicSharedMemorySize, SMEM_DYN);
    cudaFuncSetAttribute((const void*)hgemm_kernel<1>,
                         cudaFuncAttributeMaxDynamicSharedMemorySize, SMEM_DYN);
    cudaFuncSetAttribute((const void*)hgemm_kernel<2>,
                         cudaFuncAttributeMaxDynamicSharedMemorySize, SMEM_DYN);
    cudaFuncSetAttribute((const void*)hgemm_kernel<3>,
                         cudaFuncAttributeMaxDynamicSharedMemorySize, SMEM_DYN);

    float* out = (float*)d_out;

    // weight transposes to fp16 (graph-captured each launch)
    tp_kernel<<<dim3(3*DD/32, DD/32, LL), 256>>>(
        wqkv, pwqkv, DD, 3*DD, 3*DD, (size_t)DD*3*DD, (size_t)3*DD*DD);
    tp_kernel<<<dim3(DD/32, DD/32, LL), 256>>>(
        wproj, pwproj, DD, DD, DD, (size_t)DD*DD, (size_t)DD*DD);
    tp_kernel<<<dim3(4*DD/32, DD/32, LL), 256>>>(
        w1, pw1, DD, 4*DD, 4*DD, (size_t)DD*4*DD, (size_t)4*DD*DD);
    tp_kernel<<<dim3(DD/32, 4*DD/32, LL), 256>>>(
        w2, pw2, 4*DD, DD, DD, (size_t)4*DD*DD, (size_t)DD*4*DD);
    tp_kernel<<<dim3(VPAD/32, DD/32, 1), 256>>>(
        lmw, plmw, DD, VV, VPAD, 0, 0);

    embed_kernel<<<ROWS, 256>>>(idx, tok, pos, px);

    for (int l = 0; l < LL; l++) {
        ln_kernel<<<ROWS, 256>>>(px, ln1g + (size_t)l*DD, ln1b + (size_t)l*DD, ph);
        hgemm_kernel<3><<<dim3(ROWS/128, 3*DD/256), 512, SMEM_DYN>>>(
            ROWS, 3*DD, DD, ph, pwqkv + (size_t)l*3*DD*DD,
            bqkv + (size_t)l*3*DD, nullptr, nullptr, pqkvh, nullptr);
        attn_kernel<<<dim3(BB*HH, TT/64), 128>>>(pqkvh, py);
        hgemm_kernel<2><<<dim3(ROWS/128, DD/256), 512, SMEM_DYN>>>(
            ROWS, DD, DD, py, pwproj + (size_t)l*DD*DD,
            bproj + (size_t)l*DD, px, px, nullptr, nullptr);
        ln_kernel<<<ROWS, 256>>>(px, ln2g + (size_t)l*DD, ln2b + (size_t)l*DD, ph);
        hgemm_kernel<1><<<dim3(ROWS/128, 4*DD/256), 512, SMEM_DYN>>>(
            ROWS, 4*DD, DD, ph, pw1 + (size_t)l*4*DD*DD,
            b1 + (size_t)l*4*DD, nullptr, nullptr, pm, nullptr);
        hgemm_kernel<2><<<dim3(ROWS/128, DD/256), 512, SMEM_DYN>>>(
            ROWS, DD, 4*DD, pm, pw2 + (size_t)l*DD*4*DD,
            b2 + (size_t)l*DD, px, px, nullptr, nullptr);
    }

    // quantize residual, logits = x @ lm_w (+ fused logsumexp partials)
    tohalf_kernel<<<ROWS, 256>>>(px, pxh);
    hgemm_kernel<0><<<dim3(ROWS/128, VPAD/256), 512, SMEM_DYN>>>(
        ROWS, VV, DD, pxh, plmw, nullptr, nullptr, out, nullptr, ppart);

    // loss from partials
    nll_kernel<<<ROWS, 128>>>(ppart, out, tgt, pnll);
    size_t nlog = (size_t)ROWS * VV;
    if ((size_t)out_size > nlog) {
        loss_kernel<<<1, 256>>>(pnll, tgt, out + nlog);
    }
}